// round 1
// baseline (speedup 1.0000x reference)
#include <cuda_runtime.h>
#include <math.h>

#define HIDDEN 2048
#define HEADS 16
#define HEAD_DIM 128
#define BATCH 8
#define QLEN 1024
#define KVLEN 4096
#define MROWS (BATCH * QLEN) /* 8192 */

#define SCALE_F 0.08838834764831845f /* 1/sqrt(128) */

// Scratch (alloc-free rule: static device globals)
__device__ float g_Q[(size_t)MROWS * HIDDEN];
__device__ float g_attn[(size_t)MROWS * HIDDEN];

// ---------------------------------------------------------------------------
// SGEMM (NT): C[m,n] = sum_k A[m,k] * B[n,k];  M=8192, N=K=2048
// 128x128 tile, BK=8, 256 threads, 8x8 per thread, register prefetch.
// ---------------------------------------------------------------------------
__global__ __launch_bounds__(256, 2) void sgemm_nt(const float* __restrict__ A,
                                                   const float* __restrict__ B,
                                                   float* __restrict__ C) {
    __shared__ float As[8][132];
    __shared__ float Bs[8][132];
    const int tid = threadIdx.x;
    const int bm = blockIdx.y << 7;
    const int bn = blockIdx.x << 7;
    const int lr = tid >> 1;            // 0..127
    const int lk = (tid & 1) << 2;      // 0 or 4
    const float* Ap = A + (size_t)(bm + lr) * HIDDEN + lk;
    const float* Bp = B + (size_t)(bn + lr) * HIDDEN + lk;
    const int ty = tid >> 4;
    const int tx = tid & 15;

    float acc[8][8];
#pragma unroll
    for (int i = 0; i < 8; i++)
#pragma unroll
        for (int j = 0; j < 8; j++) acc[i][j] = 0.f;

    float4 a4 = *(const float4*)Ap;
    float4 b4 = *(const float4*)Bp;

    for (int k0 = 0; k0 < HIDDEN; k0 += 8) {
        As[lk + 0][lr] = a4.x; As[lk + 1][lr] = a4.y;
        As[lk + 2][lr] = a4.z; As[lk + 3][lr] = a4.w;
        Bs[lk + 0][lr] = b4.x; Bs[lk + 1][lr] = b4.y;
        Bs[lk + 2][lr] = b4.z; Bs[lk + 3][lr] = b4.w;
        __syncthreads();
        if (k0 + 8 < HIDDEN) {
            a4 = *(const float4*)(Ap + k0 + 8);
            b4 = *(const float4*)(Bp + k0 + 8);
        }
#pragma unroll
        for (int kk = 0; kk < 8; kk++) {
            float ar[8], br[8];
            *(float4*)(ar)     = *(const float4*)(&As[kk][ty * 8]);
            *(float4*)(ar + 4) = *(const float4*)(&As[kk][ty * 8 + 4]);
            *(float4*)(br)     = *(const float4*)(&Bs[kk][tx * 8]);
            *(float4*)(br + 4) = *(const float4*)(&Bs[kk][tx * 8 + 4]);
#pragma unroll
            for (int i = 0; i < 8; i++)
#pragma unroll
                for (int j = 0; j < 8; j++)
                    acc[i][j] = fmaf(ar[i], br[j], acc[i][j]);
        }
        __syncthreads();
    }

    float* Cp = C + (size_t)(bm + ty * 8) * HIDDEN + bn + tx * 8;
#pragma unroll
    for (int i = 0; i < 8; i++) {
        *(float4*)(Cp + (size_t)i * HIDDEN) =
            make_float4(acc[i][0], acc[i][1], acc[i][2], acc[i][3]);
        *(float4*)(Cp + (size_t)i * HIDDEN + 4) =
            make_float4(acc[i][4], acc[i][5], acc[i][6], acc[i][7]);
    }
}

// ---------------------------------------------------------------------------
// Flash attention, fp32. Grid: (QL/128, B*H). 256 threads (16x16).
// Q tile BQ=128 rows (pre-scaled), KV chunk BK=64, D=128.
// S thread-tile: 8 rows x 4 cols; O thread-tile: 8 rows x 8 cols.
// sQ / sK XOR-swizzled (float4-slot granularity) for conflict-free LDS.128.
// Dynamic smem: sQ 64KB | sK 32KB | sV 32KB | sP 32KB = 160KB.
// ---------------------------------------------------------------------------
__global__ __launch_bounds__(256, 1) void attn_kernel(const float* __restrict__ Qg,
                                                      const float* __restrict__ Kg,
                                                      const float* __restrict__ Vg,
                                                      float* __restrict__ Og) {
    extern __shared__ float smem[];
    float* sQ = smem;              // [128][128] swizzled
    float* sK = smem + 16384;      // [64][128]  swizzled
    float* sV = smem + 24576;      // [64][128]  linear
    float* sP = smem + 32768;      // [128][64]  linear

    const int tid = threadIdx.x;
    const int h = blockIdx.y & 15;
    const int b = blockIdx.y >> 4;
    const int q0 = blockIdx.x << 7;
    const int ty = tid >> 4;
    const int tx = tid & 15;

    // Load + scale Q tile (swizzle slot: c4 ^ ((r>>3)&7))
    {
        const float* qbase = Qg + ((size_t)(b * QLEN + q0)) * HIDDEN + h * HEAD_DIM;
#pragma unroll
        for (int it = 0; it < 16; it++) {
            int slot = tid + it * 256;
            int r = slot >> 5;
            int c4 = slot & 31;
            float4 v = *(const float4*)(qbase + (size_t)r * HIDDEN + (c4 << 2));
            v.x *= SCALE_F; v.y *= SCALE_F; v.z *= SCALE_F; v.w *= SCALE_F;
            *(float4*)(&sQ[r * 128 + ((c4 ^ ((r >> 3) & 7)) << 2)]) = v;
        }
    }

    float m_i[8], l_i[8], o[8][8];
#pragma unroll
    for (int i = 0; i < 8; i++) {
        m_i[i] = -1e30f;
        l_i[i] = 0.f;
#pragma unroll
        for (int j = 0; j < 8; j++) o[i][j] = 0.f;
    }

    const int qsw = (ty & 7) << 2;   // read swizzle for rows ty*8..ty*8+7
    const int ksw = (tx & 7) << 2;   // read swizzle for rows tx*4..tx*4+3

    for (int kb = 0; kb < KVLEN; kb += 64) {
        __syncthreads();  // previous chunk's sV/sP reads done
        {
            const float* kbase = Kg + (size_t)kb * HIDDEN + h * HEAD_DIM;
            const float* vbase = Vg + (size_t)kb * HIDDEN + h * HEAD_DIM;
#pragma unroll
            for (int it = 0; it < 8; it++) {
                int slot = tid + it * 256;   // 64 rows x 32 float4
                int r = slot >> 5;
                int c4 = slot & 31;
                size_t goff = (size_t)r * HIDDEN + (c4 << 2);
                *(float4*)(&sK[r * 128 + ((c4 ^ ((r >> 2) & 7)) << 2)]) =
                    *(const float4*)(kbase + goff);
                *(float4*)(&sV[r * 128 + (c4 << 2)]) =
                    *(const float4*)(vbase + goff);
            }
        }
        __syncthreads();

        // S = (Q*scale) @ K^T  -> acc[8][4]
        float acc[8][4];
#pragma unroll
        for (int i = 0; i < 8; i++)
#pragma unroll
            for (int j = 0; j < 4; j++) acc[i][j] = 0.f;

#pragma unroll 8
        for (int d4 = 0; d4 < 32; d4++) {
            float4 q[8], k[4];
#pragma unroll
            for (int i = 0; i < 8; i++)
                q[i] = *(const float4*)(&sQ[(ty * 8 + i) * 128 + ((d4 << 2) ^ qsw)]);
#pragma unroll
            for (int j = 0; j < 4; j++)
                k[j] = *(const float4*)(&sK[(tx * 4 + j) * 128 + ((d4 << 2) ^ ksw)]);
#pragma unroll
            for (int i = 0; i < 8; i++)
#pragma unroll
                for (int j = 0; j < 4; j++) {
                    acc[i][j] = fmaf(q[i].x, k[j].x, acc[i][j]);
                    acc[i][j] = fmaf(q[i].y, k[j].y, acc[i][j]);
                    acc[i][j] = fmaf(q[i].z, k[j].z, acc[i][j]);
                    acc[i][j] = fmaf(q[i].w, k[j].w, acc[i][j]);
                }
        }

        // Online softmax (rows owned by the 16 lanes sharing ty)
#pragma unroll
        for (int i = 0; i < 8; i++) {
            float mx = fmaxf(fmaxf(acc[i][0], acc[i][1]), fmaxf(acc[i][2], acc[i][3]));
#pragma unroll
            for (int off = 1; off < 16; off <<= 1)
                mx = fmaxf(mx, __shfl_xor_sync(0xffffffffu, mx, off, 16));
            float mnew = fmaxf(m_i[i], mx);
            float alpha = __expf(m_i[i] - mnew);
            float p0 = __expf(acc[i][0] - mnew);
            float p1 = __expf(acc[i][1] - mnew);
            float p2 = __expf(acc[i][2] - mnew);
            float p3 = __expf(acc[i][3] - mnew);
            float s = p0 + p1 + p2 + p3;
#pragma unroll
            for (int off = 1; off < 16; off <<= 1)
                s += __shfl_xor_sync(0xffffffffu, s, off, 16);
            l_i[i] = l_i[i] * alpha + s;
            m_i[i] = mnew;
#pragma unroll
            for (int j = 0; j < 8; j++) o[i][j] *= alpha;
            *(float4*)(&sP[(ty * 8 + i) * 64 + tx * 4]) = make_float4(p0, p1, p2, p3);
        }
        __syncthreads();

        // O += P @ V
#pragma unroll 4
        for (int k = 0; k < 64; k++) {
            float4 v0 = *(const float4*)(&sV[k * 128 + tx * 8]);
            float4 v1 = *(const float4*)(&sV[k * 128 + tx * 8 + 4]);
#pragma unroll
            for (int i = 0; i < 8; i++) {
                float p = sP[(ty * 8 + i) * 64 + k];
                o[i][0] = fmaf(p, v0.x, o[i][0]);
                o[i][1] = fmaf(p, v0.y, o[i][1]);
                o[i][2] = fmaf(p, v0.z, o[i][2]);
                o[i][3] = fmaf(p, v0.w, o[i][3]);
                o[i][4] = fmaf(p, v1.x, o[i][4]);
                o[i][5] = fmaf(p, v1.y, o[i][5]);
                o[i][6] = fmaf(p, v1.z, o[i][6]);
                o[i][7] = fmaf(p, v1.w, o[i][7]);
            }
        }
    }

    // Normalize and store: attn_out[b, q, h, d]
    float* obase = Og + ((size_t)(b * QLEN + q0 + ty * 8)) * HIDDEN + h * HEAD_DIM + tx * 8;
#pragma unroll
    for (int i = 0; i < 8; i++) {
        float inv = 1.0f / l_i[i];
        *(float4*)(obase + (size_t)i * HIDDEN) =
            make_float4(o[i][0] * inv, o[i][1] * inv, o[i][2] * inv, o[i][3] * inv);
        *(float4*)(obase + (size_t)i * HIDDEN + 4) =
            make_float4(o[i][4] * inv, o[i][5] * inv, o[i][6] * inv, o[i][7] * inv);
    }
}

// ---------------------------------------------------------------------------
// kernel_launch: Q-proj GEMM -> flash attention -> O-proj GEMM
// ---------------------------------------------------------------------------
extern "C" void kernel_launch(void* const* d_in, const int* in_sizes, int n_in,
                              void* d_out, int out_size) {
    const float* query = (const float*)d_in[0];  // [8,1024,2048]
    const float* kv_k  = (const float*)d_in[1];  // [32,128,2048]
    const float* kv_v  = (const float*)d_in[2];  // [32,128,2048]
    const float* Wq    = (const float*)d_in[3];  // [2048,2048]
    const float* Wo    = (const float*)d_in[4];  // [2048,2048]
    float* out = (float*)d_out;                  // [8,1024,2048]

    float *qp = nullptr, *ap = nullptr;
    cudaGetSymbolAddress((void**)&qp, g_Q);
    cudaGetSymbolAddress((void**)&ap, g_attn);

    const int ATTN_SMEM = 160 * 1024;
    cudaFuncSetAttribute(attn_kernel, cudaFuncAttributeMaxDynamicSharedMemorySize,
                         ATTN_SMEM);

    dim3 gemm_grid(HIDDEN / 128, MROWS / 128);  // (16, 64)
    sgemm_nt<<<gemm_grid, 256>>>(query, Wq, qp);

    dim3 attn_grid(QLEN / 128, BATCH * HEADS);  // (8, 128)
    attn_kernel<<<attn_grid, 256, ATTN_SMEM>>>(qp, kv_k, kv_v, ap);

    sgemm_nt<<<gemm_grid, 256>>>(ap, Wo, out);
}

// round 6
// speedup vs baseline: 1.2223x; 1.2223x over previous
#include <cuda_runtime.h>
#include <cuda_bf16.h>
#include <stdint.h>
#include <math.h>

#define HIDDEN 2048
#define HEADS 16
#define HEAD_DIM 128
#define BATCH 8
#define QLEN 1024
#define KVLEN 4096
#define MROWS (BATCH * QLEN) /* 8192 */

#define SCALE_F 0.08838834764831845f /* 1/sqrt(128) */

// ---------------------------------------------------------------------------
// Static scratch (alloc-free rule)
// ---------------------------------------------------------------------------
__device__ __nv_bfloat16 g_Ahi[(size_t)MROWS * HIDDEN];
__device__ __nv_bfloat16 g_Alo[(size_t)MROWS * HIDDEN];
__device__ __nv_bfloat16 g_Bhi[(size_t)HIDDEN * HIDDEN];
__device__ __nv_bfloat16 g_Blo[(size_t)HIDDEN * HIDDEN];
__device__ float g_Q[(size_t)MROWS * HIDDEN];
__device__ float g_attn[(size_t)MROWS * HIDDEN];

extern __shared__ __align__(16) char dyn_smem[];

// ---------------------------------------------------------------------------
// PTX helpers
// ---------------------------------------------------------------------------
__device__ __forceinline__ uint32_t smem_u32(const void* p) {
    uint32_t a;
    asm("{ .reg .u64 t; cvta.to.shared.u64 t, %1; cvt.u32.u64 %0, t; }"
        : "=r"(a) : "l"(p));
    return a;
}

__device__ __forceinline__ void cp16(uint32_t dst, const void* src) {
    asm volatile("cp.async.cg.shared.global [%0], [%1], 16;" :: "r"(dst), "l"(src));
}
#define CP_COMMIT() asm volatile("cp.async.commit_group;" ::: "memory")

__device__ __forceinline__ void ldsm4(uint32_t* r, uint32_t addr) {
    asm volatile("ldmatrix.sync.aligned.m8n8.x4.shared.b16 {%0,%1,%2,%3}, [%4];"
                 : "=r"(r[0]), "=r"(r[1]), "=r"(r[2]), "=r"(r[3]) : "r"(addr));
}

__device__ __forceinline__ void mma16816(float* d, const uint32_t* a,
                                         const uint32_t* b) {
    asm volatile(
        "mma.sync.aligned.m16n8k16.row.col.f32.bf16.bf16.f32 "
        "{%0,%1,%2,%3}, {%4,%5,%6,%7}, {%8,%9}, {%0,%1,%2,%3};"
        : "+f"(d[0]), "+f"(d[1]), "+f"(d[2]), "+f"(d[3])
        : "r"(a[0]), "r"(a[1]), "r"(a[2]), "r"(a[3]), "r"(b[0]), "r"(b[1]));
}

// ---------------------------------------------------------------------------
// fp32 -> (bf16 hi, bf16 lo) split conversion
// ---------------------------------------------------------------------------
__global__ void split_bf16(const float2* __restrict__ x,
                           __nv_bfloat162* __restrict__ hi,
                           __nv_bfloat162* __restrict__ lo, int n2) {
    int i = blockIdx.x * blockDim.x + threadIdx.x;
    int stride = gridDim.x * blockDim.x;
    for (; i < n2; i += stride) {
        float2 v = x[i];
        __nv_bfloat16 hx = __float2bfloat16(v.x);
        __nv_bfloat16 hy = __float2bfloat16(v.y);
        float lx = v.x - __bfloat162float(hx);
        float ly = v.y - __bfloat162float(hy);
        __nv_bfloat162 h; h.x = hx; h.y = hy;
        __nv_bfloat162 l; l.x = __float2bfloat16(lx); l.y = __float2bfloat16(ly);
        hi[i] = h;
        lo[i] = l;
    }
}

// ---------------------------------------------------------------------------
// bf16x3 GEMM (NT) via mma.sync m16n8k16: C[m,n] = sum_k A[m,k]*B[n,k].
// CTA tile 128x128, BK=32, 256 threads, warp grid 2(M)x4(N), warp tile 64x32.
// Smem rows: 32 bf16 = 64B data padded to 80B stride (conflict-free LDSM:
// 5r mod 8 covers all 8 bank-groups). 3-stage cp.async pipeline.
// Stage: Ahi | Alo | Bhi | Blo, each 128 rows x 80B = 10240B.
// ---------------------------------------------------------------------------
#define BK 32
#define NCHUNKS (HIDDEN / BK) /* 64 */
#define ROWB 80
#define TILE_B (128 * ROWB)      /* 10240 */
#define STAGE_B (4 * TILE_B)     /* 40960 */
#define GEMM_SMEM (3 * STAGE_B)  /* 122880 */

__global__ __launch_bounds__(256, 1) void gemm_bf16x3(
    const __nv_bfloat16* __restrict__ Ahi, const __nv_bfloat16* __restrict__ Alo,
    const __nv_bfloat16* __restrict__ Bhi, const __nv_bfloat16* __restrict__ Blo,
    float* __restrict__ C) {
    const uint32_t sbase = smem_u32(dyn_smem);
    const int tid = threadIdx.x;
    const int wid = tid >> 5;
    const int lane = tid & 31;
    const int warp_m = wid >> 2;        // 0..1
    const int warp_n = wid & 3;         // 0..3
    const int bm = blockIdx.y << 7;
    const int bn = blockIdx.x << 7;

    const __nv_bfloat16* gAh = Ahi + (size_t)bm * HIDDEN;
    const __nv_bfloat16* gAl = Alo + (size_t)bm * HIDDEN;
    const __nv_bfloat16* gBh = Bhi + (size_t)bn * HIDDEN;
    const __nv_bfloat16* gBl = Blo + (size_t)bn * HIDDEN;

    // cp.async mapping: 2 slots/thread/tile; slot -> (row, 16B col)
    const int s_r0 = tid >> 2;          // slot0 row when i=0: slot=tid
    // (computed inside loop for generality)

    auto load_chunk = [&](int c) {
        const uint32_t stg = sbase + (uint32_t)(c % 3) * STAGE_B;
        const int k0 = c * BK;
#pragma unroll
        for (int i = 0; i < 2; i++) {
            const int slot = tid + i * 256;       // 0..511
            const int r = slot >> 2;              // 0..127
            const int c16 = slot & 3;             // 16B chunk in 64B row
            const uint32_t so = (uint32_t)r * ROWB + (uint32_t)c16 * 16u;
            const size_t go = (size_t)r * HIDDEN + k0 + c16 * 8;
            cp16(stg + 0 * TILE_B + so, gAh + go);
            cp16(stg + 1 * TILE_B + so, gAl + go);
            cp16(stg + 2 * TILE_B + so, gBh + go);
            cp16(stg + 3 * TILE_B + so, gBl + go);
        }
        CP_COMMIT();
    };

    float acc[4][4][4];
#pragma unroll
    for (int mi = 0; mi < 4; mi++)
#pragma unroll
        for (int ni = 0; ni < 4; ni++)
#pragma unroll
            for (int j = 0; j < 4; j++) acc[mi][ni][j] = 0.f;

    // ldmatrix per-lane address components
    // A (.x4): lanes 0-7: rows 0-7 khalf0 | 8-15: rows 8-15 khalf0
    //          16-23: rows 0-7 khalf1    | 24-31: rows 8-15 khalf1
    const uint32_t a_off = (uint32_t)(lane & 15) * ROWB + (uint32_t)((lane >> 4) << 4);
    // B (.x4): lanes 0-7: n0-7 kh0 | 8-15: n0-7 kh1 | 16-23: n8-15 kh0 | 24-31: n8-15 kh1
    const uint32_t b_row = (uint32_t)((lane & 7) + ((lane >> 4) << 3));
    const uint32_t b_off = b_row * ROWB + (uint32_t)(((lane >> 3) & 1) << 4);

    load_chunk(0);
    load_chunk(1);

    for (int c = 0; c < NCHUNKS; c++) {
        __syncthreads();  // all warps done reading stage (c+2)%3 (chunk c-1)
        if (c + 2 < NCHUNKS) {
            load_chunk(c + 2);
            asm volatile("cp.async.wait_group 2;" ::: "memory");
        } else if (c + 1 < NCHUNKS) {
            asm volatile("cp.async.wait_group 1;" ::: "memory");
        } else {
            asm volatile("cp.async.wait_group 0;" ::: "memory");
        }
        __syncthreads();  // chunk c visible to all

        const uint32_t stg = sbase + (uint32_t)(c % 3) * STAGE_B;
        const uint32_t sAh = stg + 0 * TILE_B + (uint32_t)(warp_m * 64) * ROWB + a_off;
        const uint32_t sAl = stg + 1 * TILE_B + (uint32_t)(warp_m * 64) * ROWB + a_off;
        const uint32_t sBh = stg + 2 * TILE_B + (uint32_t)(warp_n * 32) * ROWB + b_off;
        const uint32_t sBl = stg + 3 * TILE_B + (uint32_t)(warp_n * 32) * ROWB + b_off;

#pragma unroll
        for (int ks = 0; ks < 2; ks++) {
            const uint32_t ko = (uint32_t)(ks * 32);
            uint32_t ah[4][4], al[4][4], bh[2][4], bl[2][4];
#pragma unroll
            for (int mi = 0; mi < 4; mi++) {
                ldsm4(ah[mi], sAh + (uint32_t)(mi * 16) * ROWB + ko);
                ldsm4(al[mi], sAl + (uint32_t)(mi * 16) * ROWB + ko);
            }
#pragma unroll
            for (int bi = 0; bi < 2; bi++) {
                ldsm4(bh[bi], sBh + (uint32_t)(bi * 16) * ROWB + ko);
                ldsm4(bl[bi], sBl + (uint32_t)(bi * 16) * ROWB + ko);
            }
#pragma unroll
            for (int mi = 0; mi < 4; mi++) {
#pragma unroll
                for (int ni = 0; ni < 4; ni++) {
                    const uint32_t* bhf = &bh[ni >> 1][(ni & 1) * 2];
                    const uint32_t* blf = &bl[ni >> 1][(ni & 1) * 2];
                    mma16816(acc[mi][ni], ah[mi], bhf);  // hi*hi
                    mma16816(acc[mi][ni], ah[mi], blf);  // hi*lo
                    mma16816(acc[mi][ni], al[mi], bhf);  // lo*hi
                }
            }
        }
    }

    // Epilogue: thread l of (mi,ni): rows mbase+l/4 (+8), cols nbase+2*(l%4)+{0,1}
    const int er = lane >> 2;
    const int ec = (lane & 3) * 2;
#pragma unroll
    for (int mi = 0; mi < 4; mi++) {
        const int row = bm + warp_m * 64 + mi * 16 + er;
#pragma unroll
        for (int ni = 0; ni < 4; ni++) {
            const int col = bn + warp_n * 32 + ni * 8 + ec;
            *(float2*)(C + (size_t)row * HIDDEN + col) =
                make_float2(acc[mi][ni][0], acc[mi][ni][1]);
            *(float2*)(C + (size_t)(row + 8) * HIDDEN + col) =
                make_float2(acc[mi][ni][2], acc[mi][ni][3]);
        }
    }
}

// ---------------------------------------------------------------------------
// Flash attention, fp32 (unchanged, known-good).
// ---------------------------------------------------------------------------
__global__ __launch_bounds__(256, 1) void attn_kernel(const float* __restrict__ Qg,
                                                      const float* __restrict__ Kg,
                                                      const float* __restrict__ Vg,
                                                      float* __restrict__ Og) {
    float* smem = (float*)dyn_smem;
    float* sQ = smem;              // [128][128] swizzled
    float* sK = smem + 16384;      // [64][128]  swizzled
    float* sV = smem + 24576;      // [64][128]  linear
    float* sP = smem + 32768;      // [128][64]  linear

    const int tid = threadIdx.x;
    const int h = blockIdx.y & 15;
    const int b = blockIdx.y >> 4;
    const int q0 = blockIdx.x << 7;
    const int ty = tid >> 4;
    const int tx = tid & 15;

    {
        const float* qbase = Qg + ((size_t)(b * QLEN + q0)) * HIDDEN + h * HEAD_DIM;
#pragma unroll
        for (int it = 0; it < 16; it++) {
            int slot = tid + it * 256;
            int r = slot >> 5;
            int c4 = slot & 31;
            float4 v = *(const float4*)(qbase + (size_t)r * HIDDEN + (c4 << 2));
            v.x *= SCALE_F; v.y *= SCALE_F; v.z *= SCALE_F; v.w *= SCALE_F;
            *(float4*)(&sQ[r * 128 + ((c4 ^ ((r >> 3) & 7)) << 2)]) = v;
        }
    }

    float m_i[8], l_i[8], o[8][8];
#pragma unroll
    for (int i = 0; i < 8; i++) {
        m_i[i] = -1e30f;
        l_i[i] = 0.f;
#pragma unroll
        for (int j = 0; j < 8; j++) o[i][j] = 0.f;
    }

    const int qsw = (ty & 7) << 2;
    const int ksw = (tx & 7) << 2;

    for (int kb = 0; kb < KVLEN; kb += 64) {
        __syncthreads();
        {
            const float* kbase = Kg + (size_t)kb * HIDDEN + h * HEAD_DIM;
            const float* vbase = Vg + (size_t)kb * HIDDEN + h * HEAD_DIM;
#pragma unroll
            for (int it = 0; it < 8; it++) {
                int slot = tid + it * 256;
                int r = slot >> 5;
                int c4 = slot & 31;
                size_t goff = (size_t)r * HIDDEN + (c4 << 2);
                *(float4*)(&sK[r * 128 + ((c4 ^ ((r >> 2) & 7)) << 2)]) =
                    *(const float4*)(kbase + goff);
                *(float4*)(&sV[r * 128 + (c4 << 2)]) =
                    *(const float4*)(vbase + goff);
            }
        }
        __syncthreads();

        float acc[8][4];
#pragma unroll
        for (int i = 0; i < 8; i++)
#pragma unroll
            for (int j = 0; j < 4; j++) acc[i][j] = 0.f;

#pragma unroll 8
        for (int d4 = 0; d4 < 32; d4++) {
            float4 q[8], k[4];
#pragma unroll
            for (int i = 0; i < 8; i++)
                q[i] = *(const float4*)(&sQ[(ty * 8 + i) * 128 + ((d4 << 2) ^ qsw)]);
#pragma unroll
            for (int j = 0; j < 4; j++)
                k[j] = *(const float4*)(&sK[(tx * 4 + j) * 128 + ((d4 << 2) ^ ksw)]);
#pragma unroll
            for (int i = 0; i < 8; i++)
#pragma unroll
                for (int j = 0; j < 4; j++) {
                    acc[i][j] = fmaf(q[i].x, k[j].x, acc[i][j]);
                    acc[i][j] = fmaf(q[i].y, k[j].y, acc[i][j]);
                    acc[i][j] = fmaf(q[i].z, k[j].z, acc[i][j]);
                    acc[i][j] = fmaf(q[i].w, k[j].w, acc[i][j]);
                }
        }

#pragma unroll
        for (int i = 0; i < 8; i++) {
            float mx = fmaxf(fmaxf(acc[i][0], acc[i][1]), fmaxf(acc[i][2], acc[i][3]));
#pragma unroll
            for (int off = 1; off < 16; off <<= 1)
                mx = fmaxf(mx, __shfl_xor_sync(0xffffffffu, mx, off, 16));
            float mnew = fmaxf(m_i[i], mx);
            float alpha = __expf(m_i[i] - mnew);
            float p0 = __expf(acc[i][0] - mnew);
            float p1 = __expf(acc[i][1] - mnew);
            float p2 = __expf(acc[i][2] - mnew);
            float p3 = __expf(acc[i][3] - mnew);
            float s = p0 + p1 + p2 + p3;
#pragma unroll
            for (int off = 1; off < 16; off <<= 1)
                s += __shfl_xor_sync(0xffffffffu, s, off, 16);
            l_i[i] = l_i[i] * alpha + s;
            m_i[i] = mnew;
#pragma unroll
            for (int j = 0; j < 8; j++) o[i][j] *= alpha;
            *(float4*)(&sP[(ty * 8 + i) * 64 + tx * 4]) = make_float4(p0, p1, p2, p3);
        }
        __syncthreads();

#pragma unroll 4
        for (int k = 0; k < 64; k++) {
            float4 v0 = *(const float4*)(&sV[k * 128 + tx * 8]);
            float4 v1 = *(const float4*)(&sV[k * 128 + tx * 8 + 4]);
#pragma unroll
            for (int i = 0; i < 8; i++) {
                float p = sP[(ty * 8 + i) * 64 + k];
                o[i][0] = fmaf(p, v0.x, o[i][0]);
                o[i][1] = fmaf(p, v0.y, o[i][1]);
                o[i][2] = fmaf(p, v0.z, o[i][2]);
                o[i][3] = fmaf(p, v0.w, o[i][3]);
                o[i][4] = fmaf(p, v1.x, o[i][4]);
                o[i][5] = fmaf(p, v1.y, o[i][5]);
                o[i][6] = fmaf(p, v1.z, o[i][6]);
                o[i][7] = fmaf(p, v1.w, o[i][7]);
            }
        }
    }

    float* obase = Og + ((size_t)(b * QLEN + q0 + ty * 8)) * HIDDEN + h * HEAD_DIM + tx * 8;
#pragma unroll
    for (int i = 0; i < 8; i++) {
        float inv = 1.0f / l_i[i];
        *(float4*)(obase + (size_t)i * HIDDEN) =
            make_float4(o[i][0] * inv, o[i][1] * inv, o[i][2] * inv, o[i][3] * inv);
        *(float4*)(obase + (size_t)i * HIDDEN + 4) =
            make_float4(o[i][4] * inv, o[i][5] * inv, o[i][6] * inv, o[i][7] * inv);
    }
}

// ---------------------------------------------------------------------------
// kernel_launch
// ---------------------------------------------------------------------------
extern "C" void kernel_launch(void* const* d_in, const int* in_sizes, int n_in,
                              void* d_out, int out_size) {
    const float* query = (const float*)d_in[0];
    const float* kv_k  = (const float*)d_in[1];
    const float* kv_v  = (const float*)d_in[2];
    const float* Wq    = (const float*)d_in[3];
    const float* Wo    = (const float*)d_in[4];
    float* out = (float*)d_out;

    __nv_bfloat16 *ahi, *alo, *bhi, *blo;
    float *qp, *ap;
    cudaGetSymbolAddress((void**)&ahi, g_Ahi);
    cudaGetSymbolAddress((void**)&alo, g_Alo);
    cudaGetSymbolAddress((void**)&bhi, g_Bhi);
    cudaGetSymbolAddress((void**)&blo, g_Blo);
    cudaGetSymbolAddress((void**)&qp, g_Q);
    cudaGetSymbolAddress((void**)&ap, g_attn);

    cudaFuncSetAttribute(gemm_bf16x3, cudaFuncAttributeMaxDynamicSharedMemorySize,
                         GEMM_SMEM);
    const int ATTN_SMEM = 160 * 1024;
    cudaFuncSetAttribute(attn_kernel, cudaFuncAttributeMaxDynamicSharedMemorySize,
                         ATTN_SMEM);

    const int NA2 = MROWS * HIDDEN / 2;
    const int NW2 = HIDDEN * HIDDEN / 2;
    dim3 gemm_grid(HIDDEN / 128, MROWS / 128);  // (16, 64)

    // Q projection
    split_bf16<<<1024, 256>>>((const float2*)query, (__nv_bfloat162*)ahi,
                              (__nv_bfloat162*)alo, NA2);
    split_bf16<<<512, 256>>>((const float2*)Wq, (__nv_bfloat162*)bhi,
                             (__nv_bfloat162*)blo, NW2);
    gemm_bf16x3<<<gemm_grid, 256, GEMM_SMEM>>>(ahi, alo, bhi, blo, qp);

    // Attention
    dim3 attn_grid(QLEN / 128, BATCH * HEADS);
    attn_kernel<<<attn_grid, 256, ATTN_SMEM>>>(qp, kv_k, kv_v, ap);

    // Output projection
    split_bf16<<<1024, 256>>>((const float2*)ap, (__nv_bfloat162*)ahi,
                              (__nv_bfloat162*)alo, NA2);
    split_bf16<<<512, 256>>>((const float2*)Wo, (__nv_bfloat162*)bhi,
                             (__nv_bfloat162*)blo, NW2);
    gemm_bf16x3<<<gemm_grid, 256, GEMM_SMEM>>>(ahi, alo, bhi, blo, out);
}

// round 7
// speedup vs baseline: 2.7043x; 2.2124x over previous
#include <cuda_runtime.h>
#include <cuda_bf16.h>
#include <stdint.h>
#include <math.h>

#define HIDDEN 2048
#define HEADS 16
#define HEAD_DIM 128
#define BATCH 8
#define QLEN 1024
#define KVLEN 4096
#define MROWS (BATCH * QLEN) /* 8192 */

#define SCALE_F 0.08838834764831845f /* 1/sqrt(128) */

// ---------------------------------------------------------------------------
// Static scratch (alloc-free rule)
// ---------------------------------------------------------------------------
__device__ __nv_bfloat16 g_Ahi[(size_t)MROWS * HIDDEN];
__device__ __nv_bfloat16 g_Alo[(size_t)MROWS * HIDDEN];
__device__ __nv_bfloat16 g_Bhi[(size_t)HIDDEN * HIDDEN];
__device__ __nv_bfloat16 g_Blo[(size_t)HIDDEN * HIDDEN];
__device__ __nv_bfloat16 g_Khi[(size_t)KVLEN * HIDDEN];
__device__ __nv_bfloat16 g_Klo[(size_t)KVLEN * HIDDEN];
__device__ __nv_bfloat16 g_Vhi[(size_t)KVLEN * HIDDEN];
__device__ __nv_bfloat16 g_Vlo[(size_t)KVLEN * HIDDEN];
__device__ float g_Q[(size_t)MROWS * HIDDEN];
__device__ float g_attn[(size_t)MROWS * HIDDEN];

extern __shared__ __align__(16) char dyn_smem[];

// ---------------------------------------------------------------------------
// PTX helpers
// ---------------------------------------------------------------------------
__device__ __forceinline__ uint32_t smem_u32(const void* p) {
    uint32_t a;
    asm("{ .reg .u64 t; cvta.to.shared.u64 t, %1; cvt.u32.u64 %0, t; }"
        : "=r"(a) : "l"(p));
    return a;
}

__device__ __forceinline__ void cp16(uint32_t dst, const void* src) {
    asm volatile("cp.async.cg.shared.global [%0], [%1], 16;" :: "r"(dst), "l"(src));
}
#define CP_COMMIT() asm volatile("cp.async.commit_group;" ::: "memory")

__device__ __forceinline__ void ldsm4(uint32_t* r, uint32_t addr) {
    asm volatile("ldmatrix.sync.aligned.m8n8.x4.shared.b16 {%0,%1,%2,%3}, [%4];"
                 : "=r"(r[0]), "=r"(r[1]), "=r"(r[2]), "=r"(r[3]) : "r"(addr));
}

__device__ __forceinline__ void ldsm4t(uint32_t* r, uint32_t addr) {
    asm volatile("ldmatrix.sync.aligned.m8n8.x4.trans.shared.b16 {%0,%1,%2,%3}, [%4];"
                 : "=r"(r[0]), "=r"(r[1]), "=r"(r[2]), "=r"(r[3]) : "r"(addr));
}

__device__ __forceinline__ void mma16816(float* d, const uint32_t* a,
                                         const uint32_t* b) {
    asm volatile(
        "mma.sync.aligned.m16n8k16.row.col.f32.bf16.bf16.f32 "
        "{%0,%1,%2,%3}, {%4,%5,%6,%7}, {%8,%9}, {%0,%1,%2,%3};"
        : "+f"(d[0]), "+f"(d[1]), "+f"(d[2]), "+f"(d[3])
        : "r"(a[0]), "r"(a[1]), "r"(a[2]), "r"(a[3]), "r"(b[0]), "r"(b[1]));
}

// packed bf16x2: low half = lo, high half = hi
__device__ __forceinline__ uint32_t packbf(float lo, float hi) {
    uint32_t d;
    asm("cvt.rn.bf16x2.f32 %0, %1, %2;" : "=r"(d) : "f"(hi), "f"(lo));
    return d;
}

// build P hi/lo fragment pair from two fp32 values (k-even, k-odd)
__device__ __forceinline__ void buildp(uint32_t& ph, uint32_t& pl, float a, float b) {
    float ra = a - __bfloat162float(__float2bfloat16(a));
    float rb = b - __bfloat162float(__float2bfloat16(b));
    ph = packbf(a, b);
    pl = packbf(ra, rb);
}

// ---------------------------------------------------------------------------
// fp32 -> (bf16 hi, bf16 lo) split conversion
// ---------------------------------------------------------------------------
__global__ void split_bf16(const float2* __restrict__ x,
                           __nv_bfloat162* __restrict__ hi,
                           __nv_bfloat162* __restrict__ lo, int n2) {
    int i = blockIdx.x * blockDim.x + threadIdx.x;
    int stride = gridDim.x * blockDim.x;
    for (; i < n2; i += stride) {
        float2 v = x[i];
        __nv_bfloat16 hx = __float2bfloat16(v.x);
        __nv_bfloat16 hy = __float2bfloat16(v.y);
        float lx = v.x - __bfloat162float(hx);
        float ly = v.y - __bfloat162float(hy);
        __nv_bfloat162 h; h.x = hx; h.y = hy;
        __nv_bfloat162 l; l.x = __float2bfloat16(lx); l.y = __float2bfloat16(ly);
        hi[i] = h;
        lo[i] = l;
    }
}

// ---------------------------------------------------------------------------
// bf16x3 GEMM (NT) via mma.sync m16n8k16 (validated round 6).
// ---------------------------------------------------------------------------
#define BK 32
#define NCHUNKS (HIDDEN / BK) /* 64 */
#define GROWB 80
#define GTILE_B (128 * GROWB)
#define GSTAGE_B (4 * GTILE_B)
#define GEMM_SMEM (3 * GSTAGE_B)

__global__ __launch_bounds__(256, 1) void gemm_bf16x3(
    const __nv_bfloat16* __restrict__ Ahi, const __nv_bfloat16* __restrict__ Alo,
    const __nv_bfloat16* __restrict__ Bhi, const __nv_bfloat16* __restrict__ Blo,
    float* __restrict__ C) {
    const uint32_t sbase = smem_u32(dyn_smem);
    const int tid = threadIdx.x;
    const int wid = tid >> 5;
    const int lane = tid & 31;
    const int warp_m = wid >> 2;
    const int warp_n = wid & 3;
    const int bm = blockIdx.y << 7;
    const int bn = blockIdx.x << 7;

    const __nv_bfloat16* gAh = Ahi + (size_t)bm * HIDDEN;
    const __nv_bfloat16* gAl = Alo + (size_t)bm * HIDDEN;
    const __nv_bfloat16* gBh = Bhi + (size_t)bn * HIDDEN;
    const __nv_bfloat16* gBl = Blo + (size_t)bn * HIDDEN;

    auto load_chunk = [&](int c) {
        const uint32_t stg = sbase + (uint32_t)(c % 3) * GSTAGE_B;
        const int k0 = c * BK;
#pragma unroll
        for (int i = 0; i < 2; i++) {
            const int slot = tid + i * 256;
            const int r = slot >> 2;
            const int c16 = slot & 3;
            const uint32_t so = (uint32_t)r * GROWB + (uint32_t)c16 * 16u;
            const size_t go = (size_t)r * HIDDEN + k0 + c16 * 8;
            cp16(stg + 0 * GTILE_B + so, gAh + go);
            cp16(stg + 1 * GTILE_B + so, gAl + go);
            cp16(stg + 2 * GTILE_B + so, gBh + go);
            cp16(stg + 3 * GTILE_B + so, gBl + go);
        }
        CP_COMMIT();
    };

    float acc[4][4][4];
#pragma unroll
    for (int mi = 0; mi < 4; mi++)
#pragma unroll
        for (int ni = 0; ni < 4; ni++)
#pragma unroll
            for (int j = 0; j < 4; j++) acc[mi][ni][j] = 0.f;

    const uint32_t a_off = (uint32_t)(lane & 15) * GROWB + (uint32_t)((lane >> 4) << 4);
    const uint32_t b_row = (uint32_t)((lane & 7) + ((lane >> 4) << 3));
    const uint32_t b_off = b_row * GROWB + (uint32_t)(((lane >> 3) & 1) << 4);

    load_chunk(0);
    load_chunk(1);

    for (int c = 0; c < NCHUNKS; c++) {
        __syncthreads();
        if (c + 2 < NCHUNKS) {
            load_chunk(c + 2);
            asm volatile("cp.async.wait_group 2;" ::: "memory");
        } else if (c + 1 < NCHUNKS) {
            asm volatile("cp.async.wait_group 1;" ::: "memory");
        } else {
            asm volatile("cp.async.wait_group 0;" ::: "memory");
        }
        __syncthreads();

        const uint32_t stg = sbase + (uint32_t)(c % 3) * GSTAGE_B;
        const uint32_t sAh = stg + 0 * GTILE_B + (uint32_t)(warp_m * 64) * GROWB + a_off;
        const uint32_t sAl = stg + 1 * GTILE_B + (uint32_t)(warp_m * 64) * GROWB + a_off;
        const uint32_t sBh = stg + 2 * GTILE_B + (uint32_t)(warp_n * 32) * GROWB + b_off;
        const uint32_t sBl = stg + 3 * GTILE_B + (uint32_t)(warp_n * 32) * GROWB + b_off;

#pragma unroll
        for (int ks = 0; ks < 2; ks++) {
            const uint32_t ko = (uint32_t)(ks * 32);
            uint32_t ah[4][4], al[4][4], bh[2][4], bl[2][4];
#pragma unroll
            for (int mi = 0; mi < 4; mi++) {
                ldsm4(ah[mi], sAh + (uint32_t)(mi * 16) * GROWB + ko);
                ldsm4(al[mi], sAl + (uint32_t)(mi * 16) * GROWB + ko);
            }
#pragma unroll
            for (int bi = 0; bi < 2; bi++) {
                ldsm4(bh[bi], sBh + (uint32_t)(bi * 16) * GROWB + ko);
                ldsm4(bl[bi], sBl + (uint32_t)(bi * 16) * GROWB + ko);
            }
#pragma unroll
            for (int mi = 0; mi < 4; mi++) {
#pragma unroll
                for (int ni = 0; ni < 4; ni++) {
                    const uint32_t* bhf = &bh[ni >> 1][(ni & 1) * 2];
                    const uint32_t* blf = &bl[ni >> 1][(ni & 1) * 2];
                    mma16816(acc[mi][ni], ah[mi], bhf);
                    mma16816(acc[mi][ni], ah[mi], blf);
                    mma16816(acc[mi][ni], al[mi], bhf);
                }
            }
        }
    }

    const int er = lane >> 2;
    const int ec = (lane & 3) * 2;
#pragma unroll
    for (int mi = 0; mi < 4; mi++) {
        const int row = bm + warp_m * 64 + mi * 16 + er;
#pragma unroll
        for (int ni = 0; ni < 4; ni++) {
            const int col = bn + warp_n * 32 + ni * 8 + ec;
            *(float2*)(C + (size_t)row * HIDDEN + col) =
                make_float2(acc[mi][ni][0], acc[mi][ni][1]);
            *(float2*)(C + (size_t)(row + 8) * HIDDEN + col) =
                make_float2(acc[mi][ni][2], acc[mi][ni][3]);
        }
    }
}

// ---------------------------------------------------------------------------
// HMMA flash attention, bf16 hi/lo 3-pass, fp32 accum.
// BQ=128, BK=64, 256 threads, warp grid 8(M)x1(N): warp owns 16 Q rows.
// Smem (272B row stride): Qhi|Qlo (persistent) + 2 stages of {Khi,Klo,Vhi,Vlo}.
// S-accum layout == PV A-fragment layout -> P stays in registers.
// ---------------------------------------------------------------------------
#define ROWB 272
#define QT_B (128 * ROWB)          /* 34816 */
#define KT_B (64 * ROWB)           /* 17408 */
#define STG_B (4 * KT_B)           /* 69632 */
#define ATTN_SMEM (2 * QT_B + 2 * STG_B) /* 208896 */

__global__ __launch_bounds__(256, 1) void attn_mma(
    const __nv_bfloat16* __restrict__ Qhi, const __nv_bfloat16* __restrict__ Qlo,
    const __nv_bfloat16* __restrict__ Khi, const __nv_bfloat16* __restrict__ Klo,
    const __nv_bfloat16* __restrict__ Vhi, const __nv_bfloat16* __restrict__ Vlo,
    float* __restrict__ Og) {
    const uint32_t sb = smem_u32(dyn_smem);
    const int tid = threadIdx.x;
    const int wid = tid >> 5;
    const int lane = tid & 31;
    const int h = blockIdx.y & 15;
    const int b = blockIdx.y >> 4;
    const int q0 = blockIdx.x << 7;
    const int g = lane >> 2;
    const int c = lane & 3;

    // --- issue Q tile loads (persistent) ---
    {
        const size_t qg = ((size_t)(b * QLEN + q0)) * HIDDEN + h * HEAD_DIM;
#pragma unroll
        for (int i = 0; i < 8; i++) {
            int slot = tid + i * 256;          // 0..2047
            int r = slot >> 4, c16 = slot & 15;
            uint32_t so = (uint32_t)r * ROWB + (uint32_t)c16 * 16u;
            size_t go = qg + (size_t)r * HIDDEN + c16 * 8;
            cp16(sb + so, Qhi + go);
            cp16(sb + QT_B + so, Qlo + go);
        }
        CP_COMMIT();
    }

    auto load_kv = [&](int cc) {
        const uint32_t stg = sb + 2 * QT_B + (uint32_t)(cc & 1) * STG_B;
        const int kb = cc << 6;
#pragma unroll
        for (int i = 0; i < 4; i++) {
            int slot = tid + i * 256;          // 0..1023
            int r = slot >> 4, c16 = slot & 15;
            uint32_t so = (uint32_t)r * ROWB + (uint32_t)c16 * 16u;
            size_t go = (size_t)(kb + r) * HIDDEN + h * HEAD_DIM + c16 * 8;
            cp16(stg + 0 * KT_B + so, Khi + go);
            cp16(stg + 1 * KT_B + so, Klo + go);
            cp16(stg + 2 * KT_B + so, Vhi + go);
            cp16(stg + 3 * KT_B + so, Vlo + go);
        }
        CP_COMMIT();
    };
    load_kv(0);

    // ldsm lane-address components
    const uint32_t a_off = (uint32_t)(lane & 15) * ROWB + (uint32_t)((lane >> 4) << 4);
    const uint32_t aQh = sb + (uint32_t)(16 * wid) * ROWB + a_off;
    const uint32_t aQl = aQh + QT_B;
    const uint32_t b_row = (uint32_t)((lane & 7) + ((lane >> 4) << 3));
    const uint32_t b_off = b_row * ROWB + (uint32_t)(((lane >> 3) & 1) << 4);
    const uint32_t v_row = (uint32_t)((lane & 7) + (((lane >> 3) & 1) << 3));
    const uint32_t v_off = v_row * ROWB + (uint32_t)(((lane >> 4) & 1) << 4);

    float m0 = -1e30f, m1 = -1e30f, l0 = 0.f, l1 = 0.f;
    float o[16][4];
#pragma unroll
    for (int ni = 0; ni < 16; ni++)
#pragma unroll
        for (int j = 0; j < 4; j++) o[ni][j] = 0.f;

    for (int ch = 0; ch < 64; ch++) {
        if (ch + 1 < 64) {
            load_kv(ch + 1);
            asm volatile("cp.async.wait_group 1;" ::: "memory");
        } else {
            asm volatile("cp.async.wait_group 0;" ::: "memory");
        }
        __syncthreads();

        const uint32_t stg = sb + 2 * QT_B + (uint32_t)(ch & 1) * STG_B;
        const uint32_t sKh = stg + 0 * KT_B + b_off;
        const uint32_t sKl = stg + 1 * KT_B + b_off;
        const uint32_t sVh = stg + 2 * KT_B + v_off;
        const uint32_t sVl = stg + 3 * KT_B + v_off;

        // --- S = Q K^T (3-pass) ---
        float s[8][4];
#pragma unroll
        for (int ni = 0; ni < 8; ni++)
#pragma unroll
            for (int j = 0; j < 4; j++) s[ni][j] = 0.f;

#pragma unroll
        for (int ks = 0; ks < 8; ks++) {
            const uint32_t ko = (uint32_t)(ks * 32);
            uint32_t ah[4], al[4];
            ldsm4(ah, aQh + ko);
            ldsm4(al, aQl + ko);
#pragma unroll
            for (int j = 0; j < 4; j++) {
                uint32_t bh[4], bl[4];
                ldsm4(bh, sKh + (uint32_t)(16 * j) * ROWB + ko);
                ldsm4(bl, sKl + (uint32_t)(16 * j) * ROWB + ko);
                mma16816(s[2 * j],     ah, bh + 0);
                mma16816(s[2 * j],     ah, bl + 0);
                mma16816(s[2 * j],     al, bh + 0);
                mma16816(s[2 * j + 1], ah, bh + 2);
                mma16816(s[2 * j + 1], ah, bl + 2);
                mma16816(s[2 * j + 1], al, bh + 2);
            }
        }

        // --- online softmax (warp-local; rows g, g+8 of this warp's 16) ---
        float mx0 = -1e30f, mx1 = -1e30f;
#pragma unroll
        for (int ni = 0; ni < 8; ni++) {
#pragma unroll
            for (int j = 0; j < 4; j++) s[ni][j] *= SCALE_F;
            mx0 = fmaxf(mx0, fmaxf(s[ni][0], s[ni][1]));
            mx1 = fmaxf(mx1, fmaxf(s[ni][2], s[ni][3]));
        }
        mx0 = fmaxf(mx0, __shfl_xor_sync(0xffffffffu, mx0, 1));
        mx0 = fmaxf(mx0, __shfl_xor_sync(0xffffffffu, mx0, 2));
        mx1 = fmaxf(mx1, __shfl_xor_sync(0xffffffffu, mx1, 1));
        mx1 = fmaxf(mx1, __shfl_xor_sync(0xffffffffu, mx1, 2));
        const float nm0 = fmaxf(m0, mx0);
        const float nm1 = fmaxf(m1, mx1);
        const float al0 = __expf(m0 - nm0);
        const float al1 = __expf(m1 - nm1);
        float sum0 = 0.f, sum1 = 0.f;
#pragma unroll
        for (int ni = 0; ni < 8; ni++) {
            s[ni][0] = __expf(s[ni][0] - nm0);
            s[ni][1] = __expf(s[ni][1] - nm0);
            s[ni][2] = __expf(s[ni][2] - nm1);
            s[ni][3] = __expf(s[ni][3] - nm1);
            sum0 += s[ni][0] + s[ni][1];
            sum1 += s[ni][2] + s[ni][3];
        }
        sum0 += __shfl_xor_sync(0xffffffffu, sum0, 1);
        sum0 += __shfl_xor_sync(0xffffffffu, sum0, 2);
        sum1 += __shfl_xor_sync(0xffffffffu, sum1, 1);
        sum1 += __shfl_xor_sync(0xffffffffu, sum1, 2);
        l0 = l0 * al0 + sum0;
        l1 = l1 * al1 + sum1;
        m0 = nm0;
        m1 = nm1;
#pragma unroll
        for (int ni = 0; ni < 16; ni++) {
            o[ni][0] *= al0; o[ni][1] *= al0;
            o[ni][2] *= al1; o[ni][3] *= al1;
        }

        // --- O += P V (3-pass); P fragments built in registers ---
#pragma unroll
        for (int ks = 0; ks < 4; ks++) {
            uint32_t ph[4], pl[4];
            buildp(ph[0], pl[0], s[2 * ks][0],     s[2 * ks][1]);
            buildp(ph[1], pl[1], s[2 * ks][2],     s[2 * ks][3]);
            buildp(ph[2], pl[2], s[2 * ks + 1][0], s[2 * ks + 1][1]);
            buildp(ph[3], pl[3], s[2 * ks + 1][2], s[2 * ks + 1][3]);
            const uint32_t vro = (uint32_t)(16 * ks) * ROWB;
#pragma unroll
            for (int j = 0; j < 8; j++) {
                uint32_t vh[4], vl[4];
                ldsm4t(vh, sVh + vro + (uint32_t)(32 * j));
                ldsm4t(vl, sVl + vro + (uint32_t)(32 * j));
                mma16816(o[2 * j],     ph, vh + 0);
                mma16816(o[2 * j],     ph, vl + 0);
                mma16816(o[2 * j],     pl, vh + 0);
                mma16816(o[2 * j + 1], ph, vh + 2);
                mma16816(o[2 * j + 1], ph, vl + 2);
                mma16816(o[2 * j + 1], pl, vh + 2);
            }
        }
        __syncthreads();  // stage (ch&1) free for chunk ch+2's loads
    }

    // --- epilogue ---
    const float inv0 = 1.0f / l0;
    const float inv1 = 1.0f / l1;
    const int row0 = q0 + 16 * wid + g;
    float* ob0 = Og + ((size_t)(b * QLEN + row0)) * HIDDEN + h * HEAD_DIM;
    float* ob1 = ob0 + (size_t)8 * HIDDEN;
#pragma unroll
    for (int ni = 0; ni < 16; ni++) {
        const int col = 8 * ni + 2 * c;
        *(float2*)(ob0 + col) = make_float2(o[ni][0] * inv0, o[ni][1] * inv0);
        *(float2*)(ob1 + col) = make_float2(o[ni][2] * inv1, o[ni][3] * inv1);
    }
}

// ---------------------------------------------------------------------------
// kernel_launch
// ---------------------------------------------------------------------------
extern "C" void kernel_launch(void* const* d_in, const int* in_sizes, int n_in,
                              void* d_out, int out_size) {
    const float* query = (const float*)d_in[0];
    const float* kv_k  = (const float*)d_in[1];
    const float* kv_v  = (const float*)d_in[2];
    const float* Wq    = (const float*)d_in[3];
    const float* Wo    = (const float*)d_in[4];
    float* out = (float*)d_out;

    __nv_bfloat16 *ahi, *alo, *bhi, *blo, *khi, *klo, *vhi, *vlo;
    float *qp, *ap;
    cudaGetSymbolAddress((void**)&ahi, g_Ahi);
    cudaGetSymbolAddress((void**)&alo, g_Alo);
    cudaGetSymbolAddress((void**)&bhi, g_Bhi);
    cudaGetSymbolAddress((void**)&blo, g_Blo);
    cudaGetSymbolAddress((void**)&khi, g_Khi);
    cudaGetSymbolAddress((void**)&klo, g_Klo);
    cudaGetSymbolAddress((void**)&vhi, g_Vhi);
    cudaGetSymbolAddress((void**)&vlo, g_Vlo);
    cudaGetSymbolAddress((void**)&qp, g_Q);
    cudaGetSymbolAddress((void**)&ap, g_attn);

    cudaFuncSetAttribute(gemm_bf16x3, cudaFuncAttributeMaxDynamicSharedMemorySize,
                         GEMM_SMEM);
    cudaFuncSetAttribute(attn_mma, cudaFuncAttributeMaxDynamicSharedMemorySize,
                         ATTN_SMEM);

    const int NA2 = MROWS * HIDDEN / 2;
    const int NW2 = HIDDEN * HIDDEN / 2;
    const int NKV2 = KVLEN * HIDDEN / 2;
    dim3 gemm_grid(HIDDEN / 128, MROWS / 128);  // (16, 64)

    // Q projection
    split_bf16<<<1024, 256>>>((const float2*)query, (__nv_bfloat162*)ahi,
                              (__nv_bfloat162*)alo, NA2);
    split_bf16<<<512, 256>>>((const float2*)Wq, (__nv_bfloat162*)bhi,
                             (__nv_bfloat162*)blo, NW2);
    gemm_bf16x3<<<gemm_grid, 256, GEMM_SMEM>>>(ahi, alo, bhi, blo, qp);

    // Splits for attention: Q (reuse A buffers), K, V
    split_bf16<<<1024, 256>>>((const float2*)qp, (__nv_bfloat162*)ahi,
                              (__nv_bfloat162*)alo, NA2);
    split_bf16<<<512, 256>>>((const float2*)kv_k, (__nv_bfloat162*)khi,
                             (__nv_bfloat162*)klo, NKV2);
    split_bf16<<<512, 256>>>((const float2*)kv_v, (__nv_bfloat162*)vhi,
                             (__nv_bfloat162*)vlo, NKV2);

    // Attention (HMMA)
    dim3 attn_grid(QLEN / 128, BATCH * HEADS);  // (8, 128)
    attn_mma<<<attn_grid, 256, ATTN_SMEM>>>(ahi, alo, khi, klo, vhi, vlo, ap);

    // Output projection
    split_bf16<<<1024, 256>>>((const float2*)ap, (__nv_bfloat162*)ahi,
                              (__nv_bfloat162*)alo, NA2);
    split_bf16<<<512, 256>>>((const float2*)Wo, (__nv_bfloat162*)bhi,
                             (__nv_bfloat162*)blo, NW2);
    gemm_bf16x3<<<gemm_grid, 256, GEMM_SMEM>>>(ahi, alo, bhi, blo, out);
}

// round 10
// speedup vs baseline: 2.8814x; 1.0655x over previous
#include <cuda_runtime.h>
#include <cuda_bf16.h>
#include <stdint.h>
#include <math.h>

#define HIDDEN 2048
#define HEADS 16
#define HEAD_DIM 128
#define BATCH 8
#define QLEN 1024
#define KVLEN 4096
#define MROWS (BATCH * QLEN) /* 8192 */

#define SCALE_F 0.08838834764831845f /* 1/sqrt(128) */

// ---------------------------------------------------------------------------
// Static scratch (alloc-free rule)
// ---------------------------------------------------------------------------
__device__ __nv_bfloat16 g_Ahi[(size_t)MROWS * HIDDEN];
__device__ __nv_bfloat16 g_Alo[(size_t)MROWS * HIDDEN];
__device__ __nv_bfloat16 g_Bhi[(size_t)HIDDEN * HIDDEN];
__device__ __nv_bfloat16 g_Blo[(size_t)HIDDEN * HIDDEN];
__device__ __nv_bfloat16 g_Qhi[(size_t)MROWS * HIDDEN];
__device__ __nv_bfloat16 g_Qlo[(size_t)MROWS * HIDDEN];
__device__ __nv_bfloat16 g_Khi[(size_t)KVLEN * HIDDEN];
__device__ __nv_bfloat16 g_Klo[(size_t)KVLEN * HIDDEN];
__device__ __nv_bfloat16 g_Vhi[(size_t)KVLEN * HIDDEN];
__device__ __nv_bfloat16 g_Vlo[(size_t)KVLEN * HIDDEN];

extern __shared__ __align__(16) char dyn_smem[];

// ---------------------------------------------------------------------------
// PTX helpers
// ---------------------------------------------------------------------------
__device__ __forceinline__ uint32_t smem_u32(const void* p) {
    uint32_t a;
    asm("{ .reg .u64 t; cvta.to.shared.u64 t, %1; cvt.u32.u64 %0, t; }"
        : "=r"(a) : "l"(p));
    return a;
}

__device__ __forceinline__ void cp16(uint32_t dst, const void* src) {
    asm volatile("cp.async.cg.shared.global [%0], [%1], 16;" :: "r"(dst), "l"(src));
}
#define CP_COMMIT() asm volatile("cp.async.commit_group;" ::: "memory")

__device__ __forceinline__ void ldsm4(uint32_t* r, uint32_t addr) {
    asm volatile("ldmatrix.sync.aligned.m8n8.x4.shared.b16 {%0,%1,%2,%3}, [%4];"
                 : "=r"(r[0]), "=r"(r[1]), "=r"(r[2]), "=r"(r[3]) : "r"(addr));
}

__device__ __forceinline__ void ldsm4t(uint32_t* r, uint32_t addr) {
    asm volatile("ldmatrix.sync.aligned.m8n8.x4.trans.shared.b16 {%0,%1,%2,%3}, [%4];"
                 : "=r"(r[0]), "=r"(r[1]), "=r"(r[2]), "=r"(r[3]) : "r"(addr));
}

__device__ __forceinline__ void mma16816(float* d, const uint32_t* a,
                                         const uint32_t* b) {
    asm volatile(
        "mma.sync.aligned.m16n8k16.row.col.f32.bf16.bf16.f32 "
        "{%0,%1,%2,%3}, {%4,%5,%6,%7}, {%8,%9}, {%0,%1,%2,%3};"
        : "+f"(d[0]), "+f"(d[1]), "+f"(d[2]), "+f"(d[3])
        : "r"(a[0]), "r"(a[1]), "r"(a[2]), "r"(a[3]), "r"(b[0]), "r"(b[1]));
}

// packed bf16x2: low half = first arg, high half = second arg
__device__ __forceinline__ uint32_t packbf(float lo, float hi) {
    uint32_t d;
    asm("cvt.rn.bf16x2.f32 %0, %1, %2;" : "=r"(d) : "f"(hi), "f"(lo));
    return d;
}

// build hi/lo bf16x2 pair from two fp32 values
__device__ __forceinline__ void buildp(uint32_t& ph, uint32_t& pl, float a, float b) {
    float ra = a - __bfloat162float(__float2bfloat16(a));
    float rb = b - __bfloat162float(__float2bfloat16(b));
    ph = packbf(a, b);
    pl = packbf(ra, rb);
}

// ---------------------------------------------------------------------------
// fp32 -> (bf16 hi, bf16 lo) split, float4 vectorized
// ---------------------------------------------------------------------------
__global__ void split_bf16(const float4* __restrict__ x,
                           uint2* __restrict__ hi, uint2* __restrict__ lo, int n4) {
    int i = blockIdx.x * blockDim.x + threadIdx.x;
    int stride = gridDim.x * blockDim.x;
    for (; i < n4; i += stride) {
        float4 v = x[i];
        uint32_t h0, l0, h1, l1;
        buildp(h0, l0, v.x, v.y);
        buildp(h1, l1, v.z, v.w);
        hi[i] = make_uint2(h0, h1);
        lo[i] = make_uint2(l0, l1);
    }
}

// ---------------------------------------------------------------------------
// bf16x3 GEMM (NT) via mma.sync m16n8k16: C = A B^T, fp32 accum.
// CTA 128x128, BK=64 (32 chunks), 3-stage cp.async, ONE sync per chunk.
// 256 threads, warp grid 2(M)x4(N), warp tile 64x32. Row stride 144B
// (128B data + 16B pad -> ldsm conflict-free: 16r mod 128 distinct).
// Output: fp32 (Cf) or fused bf16 hi/lo split (Chi/Clo) when Cf==nullptr.
// ---------------------------------------------------------------------------
#define BK 64
#define NCHUNKS (HIDDEN / BK) /* 32 */
#define GROWB 144
#define GTILE_B (128 * GROWB)    /* 18432 */
#define GSTAGE_B (4 * GTILE_B)   /* 73728 */
#define GEMM_SMEM (3 * GSTAGE_B) /* 221184 */

__global__ __launch_bounds__(256, 1) void gemm_bf16x3(
    const __nv_bfloat16* __restrict__ Ahi, const __nv_bfloat16* __restrict__ Alo,
    const __nv_bfloat16* __restrict__ Bhi, const __nv_bfloat16* __restrict__ Blo,
    __nv_bfloat16* __restrict__ Chi, __nv_bfloat16* __restrict__ Clo,
    float* __restrict__ Cf) {
    const uint32_t sbase = smem_u32(dyn_smem);
    const int tid = threadIdx.x;
    const int wid = tid >> 5;
    const int lane = tid & 31;
    const int warp_m = wid >> 2;
    const int warp_n = wid & 3;
    const int bm = blockIdx.y << 7;
    const int bn = blockIdx.x << 7;

    const __nv_bfloat16* gAh = Ahi + (size_t)bm * HIDDEN;
    const __nv_bfloat16* gAl = Alo + (size_t)bm * HIDDEN;
    const __nv_bfloat16* gBh = Bhi + (size_t)bn * HIDDEN;
    const __nv_bfloat16* gBl = Blo + (size_t)bn * HIDDEN;

    // 4 tiles x 128 rows x 8 c16 slots = 4096 cp16 / 256 threads
    auto load_chunk = [&](int c) {
        const uint32_t stg = sbase + (uint32_t)(c % 3) * GSTAGE_B;
        const int k0 = c * BK;
#pragma unroll
        for (int i = 0; i < 4; i++) {
            const int slot = tid + i * 256;       // 0..1023
            const int r = slot >> 3;              // 0..127
            const int c16 = slot & 7;             // 16B chunk in 128B row
            const uint32_t so = (uint32_t)r * GROWB + (uint32_t)c16 * 16u;
            const size_t go = (size_t)r * HIDDEN + k0 + c16 * 8;
            cp16(stg + 0 * GTILE_B + so, gAh + go);
            cp16(stg + 1 * GTILE_B + so, gAl + go);
            cp16(stg + 2 * GTILE_B + so, gBh + go);
            cp16(stg + 3 * GTILE_B + so, gBl + go);
        }
        CP_COMMIT();
    };

    float acc[4][4][4];
#pragma unroll
    for (int mi = 0; mi < 4; mi++)
#pragma unroll
        for (int ni = 0; ni < 4; ni++)
#pragma unroll
            for (int j = 0; j < 4; j++) acc[mi][ni][j] = 0.f;

    const uint32_t a_off = (uint32_t)(lane & 15) * GROWB + (uint32_t)((lane >> 4) << 4);
    const uint32_t b_row = (uint32_t)((lane & 7) + ((lane >> 4) << 3));
    const uint32_t b_off = b_row * GROWB + (uint32_t)(((lane >> 3) & 1) << 4);

    load_chunk(0);
    load_chunk(1);

    for (int c = 0; c < NCHUNKS; c++) {
        if (c == NCHUNKS - 1)
            asm volatile("cp.async.wait_group 0;" ::: "memory");
        else
            asm volatile("cp.async.wait_group 1;" ::: "memory");
        __syncthreads();
        // Safe to refill stage (c+2)%3 (held chunk c-1): every warp finished
        // computing c-1 before arriving at the barrier above.
        if (c + 2 < NCHUNKS) load_chunk(c + 2);

        const uint32_t stg = sbase + (uint32_t)(c % 3) * GSTAGE_B;
        const uint32_t sAh = stg + 0 * GTILE_B + (uint32_t)(warp_m * 64) * GROWB + a_off;
        const uint32_t sAl = stg + 1 * GTILE_B + (uint32_t)(warp_m * 64) * GROWB + a_off;
        const uint32_t sBh = stg + 2 * GTILE_B + (uint32_t)(warp_n * 32) * GROWB + b_off;
        const uint32_t sBl = stg + 3 * GTILE_B + (uint32_t)(warp_n * 32) * GROWB + b_off;

#pragma unroll
        for (int ks = 0; ks < 4; ks++) {
            const uint32_t ko = (uint32_t)(ks * 32);
            uint32_t ah[4][4], al[4][4], bh[2][4], bl[2][4];
#pragma unroll
            for (int mi = 0; mi < 4; mi++) {
                ldsm4(ah[mi], sAh + (uint32_t)(mi * 16) * GROWB + ko);
                ldsm4(al[mi], sAl + (uint32_t)(mi * 16) * GROWB + ko);
            }
#pragma unroll
            for (int bi = 0; bi < 2; bi++) {
                ldsm4(bh[bi], sBh + (uint32_t)(bi * 16) * GROWB + ko);
                ldsm4(bl[bi], sBl + (uint32_t)(bi * 16) * GROWB + ko);
            }
#pragma unroll
            for (int mi = 0; mi < 4; mi++) {
#pragma unroll
                for (int ni = 0; ni < 4; ni++) {
                    const uint32_t* bhf = &bh[ni >> 1][(ni & 1) * 2];
                    const uint32_t* blf = &bl[ni >> 1][(ni & 1) * 2];
                    mma16816(acc[mi][ni], ah[mi], bhf);
                    mma16816(acc[mi][ni], ah[mi], blf);
                    mma16816(acc[mi][ni], al[mi], bhf);
                }
            }
        }
    }

    const int er = lane >> 2;
    const int ec = (lane & 3) * 2;
    if (Cf) {
#pragma unroll
        for (int mi = 0; mi < 4; mi++) {
            const int row = bm + warp_m * 64 + mi * 16 + er;
#pragma unroll
            for (int ni = 0; ni < 4; ni++) {
                const int col = bn + warp_n * 32 + ni * 8 + ec;
                *(float2*)(Cf + (size_t)row * HIDDEN + col) =
                    make_float2(acc[mi][ni][0], acc[mi][ni][1]);
                *(float2*)(Cf + (size_t)(row + 8) * HIDDEN + col) =
                    make_float2(acc[mi][ni][2], acc[mi][ni][3]);
            }
        }
    } else {
#pragma unroll
        for (int mi = 0; mi < 4; mi++) {
            const int row = bm + warp_m * 64 + mi * 16 + er;
#pragma unroll
            for (int ni = 0; ni < 4; ni++) {
                const int col = bn + warp_n * 32 + ni * 8 + ec;
                uint32_t h0, l0, h1, l1;
                buildp(h0, l0, acc[mi][ni][0], acc[mi][ni][1]);
                buildp(h1, l1, acc[mi][ni][2], acc[mi][ni][3]);
                *(uint32_t*)(Chi + (size_t)row * HIDDEN + col) = h0;
                *(uint32_t*)(Clo + (size_t)row * HIDDEN + col) = l0;
                *(uint32_t*)(Chi + (size_t)(row + 8) * HIDDEN + col) = h1;
                *(uint32_t*)(Clo + (size_t)(row + 8) * HIDDEN + col) = l1;
            }
        }
    }
}

// ---------------------------------------------------------------------------
// HMMA flash attention, bf16 hi/lo 3-pass, fp32 accum (validated round 7).
// Epilogue now writes bf16 hi/lo directly for the O-projection.
// ---------------------------------------------------------------------------
#define ROWB 272
#define QT_B (128 * ROWB)          /* 34816 */
#define KT_B (64 * ROWB)           /* 17408 */
#define STG_B (4 * KT_B)           /* 69632 */
#define ATTN_SMEM (2 * QT_B + 2 * STG_B) /* 208896 */

__global__ __launch_bounds__(256, 1) void attn_mma(
    const __nv_bfloat16* __restrict__ Qhi, const __nv_bfloat16* __restrict__ Qlo,
    const __nv_bfloat16* __restrict__ Khi, const __nv_bfloat16* __restrict__ Klo,
    const __nv_bfloat16* __restrict__ Vhi, const __nv_bfloat16* __restrict__ Vlo,
    __nv_bfloat16* __restrict__ Ohi, __nv_bfloat16* __restrict__ Olo) {
    const uint32_t sb = smem_u32(dyn_smem);
    const int tid = threadIdx.x;
    const int wid = tid >> 5;
    const int lane = tid & 31;
    const int h = blockIdx.y & 15;
    const int b = blockIdx.y >> 4;
    const int q0 = blockIdx.x << 7;
    const int g = lane >> 2;
    const int c = lane & 3;

    {
        const size_t qg = ((size_t)(b * QLEN + q0)) * HIDDEN + h * HEAD_DIM;
#pragma unroll
        for (int i = 0; i < 8; i++) {
            int slot = tid + i * 256;
            int r = slot >> 4, c16 = slot & 15;
            uint32_t so = (uint32_t)r * ROWB + (uint32_t)c16 * 16u;
            size_t go = qg + (size_t)r * HIDDEN + c16 * 8;
            cp16(sb + so, Qhi + go);
            cp16(sb + QT_B + so, Qlo + go);
        }
        CP_COMMIT();
    }

    auto load_kv = [&](int cc) {
        const uint32_t stg = sb + 2 * QT_B + (uint32_t)(cc & 1) * STG_B;
        const int kb = cc << 6;
#pragma unroll
        for (int i = 0; i < 4; i++) {
            int slot = tid + i * 256;
            int r = slot >> 4, c16 = slot & 15;
            uint32_t so = (uint32_t)r * ROWB + (uint32_t)c16 * 16u;
            size_t go = (size_t)(kb + r) * HIDDEN + h * HEAD_DIM + c16 * 8;
            cp16(stg + 0 * KT_B + so, Khi + go);
            cp16(stg + 1 * KT_B + so, Klo + go);
            cp16(stg + 2 * KT_B + so, Vhi + go);
            cp16(stg + 3 * KT_B + so, Vlo + go);
        }
        CP_COMMIT();
    };
    load_kv(0);

    const uint32_t a_off = (uint32_t)(lane & 15) * ROWB + (uint32_t)((lane >> 4) << 4);
    const uint32_t aQh = sb + (uint32_t)(16 * wid) * ROWB + a_off;
    const uint32_t aQl = aQh + QT_B;
    const uint32_t b_row = (uint32_t)((lane & 7) + ((lane >> 4) << 3));
    const uint32_t b_off = b_row * ROWB + (uint32_t)(((lane >> 3) & 1) << 4);
    const uint32_t v_row = (uint32_t)((lane & 7) + (((lane >> 3) & 1) << 3));
    const uint32_t v_off = v_row * ROWB + (uint32_t)(((lane >> 4) & 1) << 4);

    float m0 = -1e30f, m1 = -1e30f, l0 = 0.f, l1 = 0.f;
    float o[16][4];
#pragma unroll
    for (int ni = 0; ni < 16; ni++)
#pragma unroll
        for (int j = 0; j < 4; j++) o[ni][j] = 0.f;

    for (int ch = 0; ch < 64; ch++) {
        if (ch + 1 < 64) {
            load_kv(ch + 1);
            asm volatile("cp.async.wait_group 1;" ::: "memory");
        } else {
            asm volatile("cp.async.wait_group 0;" ::: "memory");
        }
        __syncthreads();

        const uint32_t stg = sb + 2 * QT_B + (uint32_t)(ch & 1) * STG_B;
        const uint32_t sKh = stg + 0 * KT_B + b_off;
        const uint32_t sKl = stg + 1 * KT_B + b_off;
        const uint32_t sVh = stg + 2 * KT_B + v_off;
        const uint32_t sVl = stg + 3 * KT_B + v_off;

        float s[8][4];
#pragma unroll
        for (int ni = 0; ni < 8; ni++)
#pragma unroll
            for (int j = 0; j < 4; j++) s[ni][j] = 0.f;

#pragma unroll
        for (int ks = 0; ks < 8; ks++) {
            const uint32_t ko = (uint32_t)(ks * 32);
            uint32_t ah[4], al[4];
            ldsm4(ah, aQh + ko);
            ldsm4(al, aQl + ko);
#pragma unroll
            for (int j = 0; j < 4; j++) {
                uint32_t bh[4], bl[4];
                ldsm4(bh, sKh + (uint32_t)(16 * j) * ROWB + ko);
                ldsm4(bl, sKl + (uint32_t)(16 * j) * ROWB + ko);
                mma16816(s[2 * j],     ah, bh + 0);
                mma16816(s[2 * j],     ah, bl + 0);
                mma16816(s[2 * j],     al, bh + 0);
                mma16816(s[2 * j + 1], ah, bh + 2);
                mma16816(s[2 * j + 1], ah, bl + 2);
                mma16816(s[2 * j + 1], al, bh + 2);
            }
        }

        float mx0 = -1e30f, mx1 = -1e30f;
#pragma unroll
        for (int ni = 0; ni < 8; ni++) {
#pragma unroll
            for (int j = 0; j < 4; j++) s[ni][j] *= SCALE_F;
            mx0 = fmaxf(mx0, fmaxf(s[ni][0], s[ni][1]));
            mx1 = fmaxf(mx1, fmaxf(s[ni][2], s[ni][3]));
        }
        mx0 = fmaxf(mx0, __shfl_xor_sync(0xffffffffu, mx0, 1));
        mx0 = fmaxf(mx0, __shfl_xor_sync(0xffffffffu, mx0, 2));
        mx1 = fmaxf(mx1, __shfl_xor_sync(0xffffffffu, mx1, 1));
        mx1 = fmaxf(mx1, __shfl_xor_sync(0xffffffffu, mx1, 2));
        const float nm0 = fmaxf(m0, mx0);
        const float nm1 = fmaxf(m1, mx1);
        const float al0 = __expf(m0 - nm0);
        const float al1 = __expf(m1 - nm1);
        float sum0 = 0.f, sum1 = 0.f;
#pragma unroll
        for (int ni = 0; ni < 8; ni++) {
            s[ni][0] = __expf(s[ni][0] - nm0);
            s[ni][1] = __expf(s[ni][1] - nm0);
            s[ni][2] = __expf(s[ni][2] - nm1);
            s[ni][3] = __expf(s[ni][3] - nm1);
            sum0 += s[ni][0] + s[ni][1];
            sum1 += s[ni][2] + s[ni][3];
        }
        sum0 += __shfl_xor_sync(0xffffffffu, sum0, 1);
        sum0 += __shfl_xor_sync(0xffffffffu, sum0, 2);
        sum1 += __shfl_xor_sync(0xffffffffu, sum1, 1);
        sum1 += __shfl_xor_sync(0xffffffffu, sum1, 2);
        l0 = l0 * al0 + sum0;
        l1 = l1 * al1 + sum1;
        m0 = nm0;
        m1 = nm1;
#pragma unroll
        for (int ni = 0; ni < 16; ni++) {
            o[ni][0] *= al0; o[ni][1] *= al0;
            o[ni][2] *= al1; o[ni][3] *= al1;
        }

#pragma unroll
        for (int ks = 0; ks < 4; ks++) {
            uint32_t ph[4], pl[4];
            buildp(ph[0], pl[0], s[2 * ks][0],     s[2 * ks][1]);
            buildp(ph[1], pl[1], s[2 * ks][2],     s[2 * ks][3]);
            buildp(ph[2], pl[2], s[2 * ks + 1][0], s[2 * ks + 1][1]);
            buildp(ph[3], pl[3], s[2 * ks + 1][2], s[2 * ks + 1][3]);
            const uint32_t vro = (uint32_t)(16 * ks) * ROWB;
#pragma unroll
            for (int j = 0; j < 8; j++) {
                uint32_t vh[4], vl[4];
                ldsm4t(vh, sVh + vro + (uint32_t)(32 * j));
                ldsm4t(vl, sVl + vro + (uint32_t)(32 * j));
                mma16816(o[2 * j],     ph, vh + 0);
                mma16816(o[2 * j],     ph, vl + 0);
                mma16816(o[2 * j],     pl, vh + 0);
                mma16816(o[2 * j + 1], ph, vh + 2);
                mma16816(o[2 * j + 1], ph, vl + 2);
                mma16816(o[2 * j + 1], pl, vh + 2);
            }
        }
        __syncthreads();
    }

    // epilogue: normalized O -> fused bf16 hi/lo
    const float inv0 = 1.0f / l0;
    const float inv1 = 1.0f / l1;
    const int row0 = q0 + 16 * wid + g;
    const size_t base0 = ((size_t)(b * QLEN + row0)) * HIDDEN + h * HEAD_DIM;
    const size_t base1 = base0 + (size_t)8 * HIDDEN;
#pragma unroll
    for (int ni = 0; ni < 16; ni++) {
        const int col = 8 * ni + 2 * c;
        uint32_t h0, l0b, h1, l1b;
        buildp(h0, l0b, o[ni][0] * inv0, o[ni][1] * inv0);
        buildp(h1, l1b, o[ni][2] * inv1, o[ni][3] * inv1);
        *(uint32_t*)(Ohi + base0 + col) = h0;
        *(uint32_t*)(Olo + base0 + col) = l0b;
        *(uint32_t*)(Ohi + base1 + col) = h1;
        *(uint32_t*)(Olo + base1 + col) = l1b;
    }
}

// ---------------------------------------------------------------------------
// kernel_launch
// ---------------------------------------------------------------------------
extern "C" void kernel_launch(void* const* d_in, const int* in_sizes, int n_in,
                              void* d_out, int out_size) {
    const float* query = (const float*)d_in[0];
    const float* kv_k  = (const float*)d_in[1];
    const float* kv_v  = (const float*)d_in[2];
    const float* Wq    = (const float*)d_in[3];
    const float* Wo    = (const float*)d_in[4];
    float* out = (float*)d_out;

    __nv_bfloat16 *ahi, *alo, *bhi, *blo, *qhi, *qlo, *khi, *klo, *vhi, *vlo;
    cudaGetSymbolAddress((void**)&ahi, g_Ahi);
    cudaGetSymbolAddress((void**)&alo, g_Alo);
    cudaGetSymbolAddress((void**)&bhi, g_Bhi);
    cudaGetSymbolAddress((void**)&blo, g_Blo);
    cudaGetSymbolAddress((void**)&qhi, g_Qhi);
    cudaGetSymbolAddress((void**)&qlo, g_Qlo);
    cudaGetSymbolAddress((void**)&khi, g_Khi);
    cudaGetSymbolAddress((void**)&klo, g_Klo);
    cudaGetSymbolAddress((void**)&vhi, g_Vhi);
    cudaGetSymbolAddress((void**)&vlo, g_Vlo);

    cudaFuncSetAttribute(gemm_bf16x3, cudaFuncAttributeMaxDynamicSharedMemorySize,
                         GEMM_SMEM);
    cudaFuncSetAttribute(attn_mma, cudaFuncAttributeMaxDynamicSharedMemorySize,
                         ATTN_SMEM);

    const int NA4 = MROWS * HIDDEN / 4;
    const int NW4 = HIDDEN * HIDDEN / 4;
    const int NKV4 = KVLEN * HIDDEN / 4;
    dim3 gemm_grid(HIDDEN / 128, MROWS / 128);  // (16, 64)

    // Q projection (epilogue writes bf16 hi/lo directly)
    split_bf16<<<2048, 256>>>((const float4*)query, (uint2*)ahi, (uint2*)alo, NA4);
    split_bf16<<<1024, 256>>>((const float4*)Wq, (uint2*)bhi, (uint2*)blo, NW4);
    gemm_bf16x3<<<gemm_grid, 256, GEMM_SMEM>>>(ahi, alo, bhi, blo,
                                               qhi, qlo, nullptr);

    // KV splits
    split_bf16<<<1024, 256>>>((const float4*)kv_k, (uint2*)khi, (uint2*)klo, NKV4);
    split_bf16<<<1024, 256>>>((const float4*)kv_v, (uint2*)vhi, (uint2*)vlo, NKV4);

    // Attention (epilogue writes bf16 hi/lo into A buffers)
    dim3 attn_grid(QLEN / 128, BATCH * HEADS);  // (8, 128)
    attn_mma<<<attn_grid, 256, ATTN_SMEM>>>(qhi, qlo, khi, klo, vhi, vlo, ahi, alo);

    // Output projection (fp32 out)
    split_bf16<<<1024, 256>>>((const float4*)Wo, (uint2*)bhi, (uint2*)blo, NW4);
    gemm_bf16x3<<<gemm_grid, 256, GEMM_SMEM>>>(ahi, alo, bhi, blo,
                                               nullptr, nullptr, out);
}

// round 14
// speedup vs baseline: 2.8919x; 1.0036x over previous
#include <cuda_runtime.h>
#include <cuda_bf16.h>
#include <stdint.h>
#include <math.h>

#define HIDDEN 2048
#define HEADS 16
#define HEAD_DIM 128
#define BATCH 8
#define QLEN 1024
#define KVLEN 4096
#define MROWS (BATCH * QLEN) /* 8192 */

#define SCALE_F 0.08838834764831845f /* 1/sqrt(128) */

// ---------------------------------------------------------------------------
// Static scratch (alloc-free rule)
// ---------------------------------------------------------------------------
__device__ __nv_bfloat16 g_Ahi[(size_t)MROWS * HIDDEN];
__device__ __nv_bfloat16 g_Alo[(size_t)MROWS * HIDDEN];
__device__ __nv_bfloat16 g_Bhi[(size_t)HIDDEN * HIDDEN];
__device__ __nv_bfloat16 g_Blo[(size_t)HIDDEN * HIDDEN];
__device__ __nv_bfloat16 g_Qhi[(size_t)MROWS * HIDDEN];
__device__ __nv_bfloat16 g_Qlo[(size_t)MROWS * HIDDEN];
__device__ __nv_bfloat16 g_Khi[(size_t)KVLEN * HIDDEN];
__device__ __nv_bfloat16 g_Klo[(size_t)KVLEN * HIDDEN];
__device__ __nv_bfloat16 g_Vhi[(size_t)KVLEN * HIDDEN];
__device__ __nv_bfloat16 g_Vlo[(size_t)KVLEN * HIDDEN];

extern __shared__ __align__(16) char dyn_smem[];

// ---------------------------------------------------------------------------
// PTX helpers
// ---------------------------------------------------------------------------
__device__ __forceinline__ uint32_t smem_u32(const void* p) {
    uint32_t a;
    asm("{ .reg .u64 t; cvta.to.shared.u64 t, %1; cvt.u32.u64 %0, t; }"
        : "=r"(a) : "l"(p));
    return a;
}

__device__ __forceinline__ void cp16(uint32_t dst, const void* src) {
    asm volatile("cp.async.cg.shared.global [%0], [%1], 16;" :: "r"(dst), "l"(src));
}
#define CP_COMMIT() asm volatile("cp.async.commit_group;" ::: "memory")

__device__ __forceinline__ void ldsm4(uint32_t* r, uint32_t addr) {
    asm volatile("ldmatrix.sync.aligned.m8n8.x4.shared.b16 {%0,%1,%2,%3}, [%4];"
                 : "=r"(r[0]), "=r"(r[1]), "=r"(r[2]), "=r"(r[3]) : "r"(addr));
}

__device__ __forceinline__ void ldsm4t(uint32_t* r, uint32_t addr) {
    asm volatile("ldmatrix.sync.aligned.m8n8.x4.trans.shared.b16 {%0,%1,%2,%3}, [%4];"
                 : "=r"(r[0]), "=r"(r[1]), "=r"(r[2]), "=r"(r[3]) : "r"(addr));
}

__device__ __forceinline__ void mma16816(float* d, const uint32_t* a,
                                         const uint32_t* b) {
    asm volatile(
        "mma.sync.aligned.m16n8k16.row.col.f32.bf16.bf16.f32 "
        "{%0,%1,%2,%3}, {%4,%5,%6,%7}, {%8,%9}, {%0,%1,%2,%3};"
        : "+f"(d[0]), "+f"(d[1]), "+f"(d[2]), "+f"(d[3])
        : "r"(a[0]), "r"(a[1]), "r"(a[2]), "r"(a[3]), "r"(b[0]), "r"(b[1]));
}

// packed bf16x2: low half = first arg, high half = second arg
__device__ __forceinline__ uint32_t packbf(float lo, float hi) {
    uint32_t d;
    asm("cvt.rn.bf16x2.f32 %0, %1, %2;" : "=r"(d) : "f"(hi), "f"(lo));
    return d;
}

// build hi/lo bf16x2 pair from two fp32 values
__device__ __forceinline__ void buildp(uint32_t& ph, uint32_t& pl, float a, float b) {
    float ra = a - __bfloat162float(__float2bfloat16(a));
    float rb = b - __bfloat162float(__float2bfloat16(b));
    ph = packbf(a, b);
    pl = packbf(ra, rb);
}

// ---------------------------------------------------------------------------
// fp32 -> (bf16 hi, bf16 lo) split, float4 vectorized
// ---------------------------------------------------------------------------
__global__ void split_bf16(const float4* __restrict__ x,
                           uint2* __restrict__ hi, uint2* __restrict__ lo, int n4) {
    int i = blockIdx.x * blockDim.x + threadIdx.x;
    int stride = gridDim.x * blockDim.x;
    for (; i < n4; i += stride) {
        float4 v = x[i];
        uint32_t h0, l0, h1, l1;
        buildp(h0, l0, v.x, v.y);
        buildp(h1, l1, v.z, v.w);
        hi[i] = make_uint2(h0, h1);
        lo[i] = make_uint2(l0, l1);
    }
}

// ---------------------------------------------------------------------------
// bf16x3 GEMM (NT) via mma.sync m16n8k16 (validated round 10, unchanged).
// ---------------------------------------------------------------------------
#define BK 64
#define NCHUNKS (HIDDEN / BK) /* 32 */
#define GROWB 144
#define GTILE_B (128 * GROWB)    /* 18432 */
#define GSTAGE_B (4 * GTILE_B)   /* 73728 */
#define GEMM_SMEM (3 * GSTAGE_B) /* 221184 */

__global__ __launch_bounds__(256, 1) void gemm_bf16x3(
    const __nv_bfloat16* __restrict__ Ahi, const __nv_bfloat16* __restrict__ Alo,
    const __nv_bfloat16* __restrict__ Bhi, const __nv_bfloat16* __restrict__ Blo,
    __nv_bfloat16* __restrict__ Chi, __nv_bfloat16* __restrict__ Clo,
    float* __restrict__ Cf) {
    const uint32_t sbase = smem_u32(dyn_smem);
    const int tid = threadIdx.x;
    const int wid = tid >> 5;
    const int lane = tid & 31;
    const int warp_m = wid >> 2;
    const int warp_n = wid & 3;
    const int bm = blockIdx.y << 7;
    const int bn = blockIdx.x << 7;

    const __nv_bfloat16* gAh = Ahi + (size_t)bm * HIDDEN;
    const __nv_bfloat16* gAl = Alo + (size_t)bm * HIDDEN;
    const __nv_bfloat16* gBh = Bhi + (size_t)bn * HIDDEN;
    const __nv_bfloat16* gBl = Blo + (size_t)bn * HIDDEN;

    auto load_chunk = [&](int c) {
        const uint32_t stg = sbase + (uint32_t)(c % 3) * GSTAGE_B;
        const int k0 = c * BK;
#pragma unroll
        for (int i = 0; i < 4; i++) {
            const int slot = tid + i * 256;
            const int r = slot >> 3;
            const int c16 = slot & 7;
            const uint32_t so = (uint32_t)r * GROWB + (uint32_t)c16 * 16u;
            const size_t go = (size_t)r * HIDDEN + k0 + c16 * 8;
            cp16(stg + 0 * GTILE_B + so, gAh + go);
            cp16(stg + 1 * GTILE_B + so, gAl + go);
            cp16(stg + 2 * GTILE_B + so, gBh + go);
            cp16(stg + 3 * GTILE_B + so, gBl + go);
        }
        CP_COMMIT();
    };

    float acc[4][4][4];
#pragma unroll
    for (int mi = 0; mi < 4; mi++)
#pragma unroll
        for (int ni = 0; ni < 4; ni++)
#pragma unroll
            for (int j = 0; j < 4; j++) acc[mi][ni][j] = 0.f;

    const uint32_t a_off = (uint32_t)(lane & 15) * GROWB + (uint32_t)((lane >> 4) << 4);
    const uint32_t b_row = (uint32_t)((lane & 7) + ((lane >> 4) << 3));
    const uint32_t b_off = b_row * GROWB + (uint32_t)(((lane >> 3) & 1) << 4);

    load_chunk(0);
    load_chunk(1);

    for (int c = 0; c < NCHUNKS; c++) {
        if (c == NCHUNKS - 1)
            asm volatile("cp.async.wait_group 0;" ::: "memory");
        else
            asm volatile("cp.async.wait_group 1;" ::: "memory");
        __syncthreads();
        if (c + 2 < NCHUNKS) load_chunk(c + 2);

        const uint32_t stg = sbase + (uint32_t)(c % 3) * GSTAGE_B;
        const uint32_t sAh = stg + 0 * GTILE_B + (uint32_t)(warp_m * 64) * GROWB + a_off;
        const uint32_t sAl = stg + 1 * GTILE_B + (uint32_t)(warp_m * 64) * GROWB + a_off;
        const uint32_t sBh = stg + 2 * GTILE_B + (uint32_t)(warp_n * 32) * GROWB + b_off;
        const uint32_t sBl = stg + 3 * GTILE_B + (uint32_t)(warp_n * 32) * GROWB + b_off;

#pragma unroll
        for (int ks = 0; ks < 4; ks++) {
            const uint32_t ko = (uint32_t)(ks * 32);
            uint32_t ah[4][4], al[4][4], bh[2][4], bl[2][4];
#pragma unroll
            for (int mi = 0; mi < 4; mi++) {
                ldsm4(ah[mi], sAh + (uint32_t)(mi * 16) * GROWB + ko);
                ldsm4(al[mi], sAl + (uint32_t)(mi * 16) * GROWB + ko);
            }
#pragma unroll
            for (int bi = 0; bi < 2; bi++) {
                ldsm4(bh[bi], sBh + (uint32_t)(bi * 16) * GROWB + ko);
                ldsm4(bl[bi], sBl + (uint32_t)(bi * 16) * GROWB + ko);
            }
#pragma unroll
            for (int mi = 0; mi < 4; mi++) {
#pragma unroll
                for (int ni = 0; ni < 4; ni++) {
                    const uint32_t* bhf = &bh[ni >> 1][(ni & 1) * 2];
                    const uint32_t* blf = &bl[ni >> 1][(ni & 1) * 2];
                    mma16816(acc[mi][ni], ah[mi], bhf);
                    mma16816(acc[mi][ni], ah[mi], blf);
                    mma16816(acc[mi][ni], al[mi], bhf);
                }
            }
        }
    }

    const int er = lane >> 2;
    const int ec = (lane & 3) * 2;
    if (Cf) {
#pragma unroll
        for (int mi = 0; mi < 4; mi++) {
            const int row = bm + warp_m * 64 + mi * 16 + er;
#pragma unroll
            for (int ni = 0; ni < 4; ni++) {
                const int col = bn + warp_n * 32 + ni * 8 + ec;
                *(float2*)(Cf + (size_t)row * HIDDEN + col) =
                    make_float2(acc[mi][ni][0], acc[mi][ni][1]);
                *(float2*)(Cf + (size_t)(row + 8) * HIDDEN + col) =
                    make_float2(acc[mi][ni][2], acc[mi][ni][3]);
            }
        }
    } else {
#pragma unroll
        for (int mi = 0; mi < 4; mi++) {
            const int row = bm + warp_m * 64 + mi * 16 + er;
#pragma unroll
            for (int ni = 0; ni < 4; ni++) {
                const int col = bn + warp_n * 32 + ni * 8 + ec;
                uint32_t h0, l0, h1, l1;
                buildp(h0, l0, acc[mi][ni][0], acc[mi][ni][1]);
                buildp(h1, l1, acc[mi][ni][2], acc[mi][ni][3]);
                *(uint32_t*)(Chi + (size_t)row * HIDDEN + col) = h0;
                *(uint32_t*)(Clo + (size_t)row * HIDDEN + col) = l0;
                *(uint32_t*)(Chi + (size_t)(row + 8) * HIDDEN + col) = h1;
                *(uint32_t*)(Clo + (size_t)(row + 8) * HIDDEN + col) = l1;
            }
        }
    }
}

// ---------------------------------------------------------------------------
// HMMA flash attention, bf16 hi/lo 3-pass, fp32 accum.
// Round 11: Q fragments persistent in registers (loaded once from a staging
// area that is then recycled as KV stage 0); 3-stage KV cp.async pipeline with
// ONE __syncthreads per chunk (GEMM-style schedule).
// Smem = 3 stages x {Khi,Klo,Vhi,Vlo} x 64 rows x 272B = 208896 B.
// ---------------------------------------------------------------------------
#define ROWB 272
#define QT_B (128 * ROWB)          /* 34816 */
#define KT_B (64 * ROWB)           /* 17408 */
#define STG_B (4 * KT_B)           /* 69632 */
#define ATTN_SMEM (3 * STG_B)      /* 208896 */

__global__ __launch_bounds__(256, 1) void attn_mma(
    const __nv_bfloat16* __restrict__ Qhi, const __nv_bfloat16* __restrict__ Qlo,
    const __nv_bfloat16* __restrict__ Khi, const __nv_bfloat16* __restrict__ Klo,
    const __nv_bfloat16* __restrict__ Vhi, const __nv_bfloat16* __restrict__ Vlo,
    __nv_bfloat16* __restrict__ Ohi, __nv_bfloat16* __restrict__ Olo) {
    const uint32_t sb = smem_u32(dyn_smem);
    const int tid = threadIdx.x;
    const int wid = tid >> 5;
    const int lane = tid & 31;
    const int h = blockIdx.y & 15;
    const int b = blockIdx.y >> 4;
    const int q0 = blockIdx.x << 7;
    const int g = lane >> 2;
    const int c = lane & 3;

    // --- stage Q (hi at sb, lo at sb+QT_B; together they fit in stage 0+1) ---
    {
        const size_t qg = ((size_t)(b * QLEN + q0)) * HIDDEN + h * HEAD_DIM;
#pragma unroll
        for (int i = 0; i < 8; i++) {
            int slot = tid + i * 256;
            int r = slot >> 4, c16 = slot & 15;
            uint32_t so = (uint32_t)r * ROWB + (uint32_t)c16 * 16u;
            size_t go = qg + (size_t)r * HIDDEN + c16 * 8;
            cp16(sb + so, Qhi + go);
            cp16(sb + QT_B + so, Qlo + go);
        }
        CP_COMMIT();
    }

    // ldsm lane-address components
    const uint32_t a_off = (uint32_t)(lane & 15) * ROWB + (uint32_t)((lane >> 4) << 4);
    const uint32_t b_row = (uint32_t)((lane & 7) + ((lane >> 4) << 3));
    const uint32_t b_off = b_row * ROWB + (uint32_t)(((lane >> 3) & 1) << 4);
    const uint32_t v_row = (uint32_t)((lane & 7) + (((lane >> 3) & 1) << 3));
    const uint32_t v_off = v_row * ROWB + (uint32_t)(((lane >> 4) & 1) << 4);

    // --- load Q fragments into persistent registers ---
    uint32_t qh[8][4], ql[8][4];
    {
        asm volatile("cp.async.wait_group 0;" ::: "memory");
        __syncthreads();
        const uint32_t aQh = sb + (uint32_t)(16 * wid) * ROWB + a_off;
        const uint32_t aQl = aQh + QT_B;
#pragma unroll
        for (int ks = 0; ks < 8; ks++) {
            ldsm4(qh[ks], aQh + (uint32_t)(ks * 32));
            ldsm4(ql[ks], aQl + (uint32_t)(ks * 32));
        }
        __syncthreads();  // Q region may now be recycled as KV stage 0
    }

    auto load_kv = [&](int cc) {
        const uint32_t stg = sb + (uint32_t)(cc % 3) * STG_B;
        const int kb = cc << 6;
#pragma unroll
        for (int i = 0; i < 4; i++) {
            int slot = tid + i * 256;
            int r = slot >> 4, c16 = slot & 15;
            uint32_t so = (uint32_t)r * ROWB + (uint32_t)c16 * 16u;
            size_t go = (size_t)(kb + r) * HIDDEN + h * HEAD_DIM + c16 * 8;
            cp16(stg + 0 * KT_B + so, Khi + go);
            cp16(stg + 1 * KT_B + so, Klo + go);
            cp16(stg + 2 * KT_B + so, Vhi + go);
            cp16(stg + 3 * KT_B + so, Vlo + go);
        }
        CP_COMMIT();
    };
    load_kv(0);
    load_kv(1);

    float m0 = -1e30f, m1 = -1e30f, l0 = 0.f, l1 = 0.f;
    float o[16][4];
#pragma unroll
    for (int ni = 0; ni < 16; ni++)
#pragma unroll
        for (int j = 0; j < 4; j++) o[ni][j] = 0.f;

    for (int ch = 0; ch < 64; ch++) {
        if (ch == 63)
            asm volatile("cp.async.wait_group 0;" ::: "memory");
        else
            asm volatile("cp.async.wait_group 1;" ::: "memory");
        __syncthreads();
        // Refill stage (ch+2)%3 (held ch-1; everyone finished it before the
        // barrier above).
        if (ch + 2 < 64) load_kv(ch + 2);

        const uint32_t stg = sb + (uint32_t)(ch % 3) * STG_B;
        const uint32_t sKh = stg + 0 * KT_B + b_off;
        const uint32_t sKl = stg + 1 * KT_B + b_off;
        const uint32_t sVh = stg + 2 * KT_B + v_off;
        const uint32_t sVl = stg + 3 * KT_B + v_off;

        // --- S = Q K^T (3-pass), Q frags from registers ---
        float s[8][4];
#pragma unroll
        for (int ni = 0; ni < 8; ni++)
#pragma unroll
            for (int j = 0; j < 4; j++) s[ni][j] = 0.f;

#pragma unroll
        for (int ks = 0; ks < 8; ks++) {
            const uint32_t ko = (uint32_t)(ks * 32);
#pragma unroll
            for (int j = 0; j < 4; j++) {
                uint32_t bh[4], bl[4];
                ldsm4(bh, sKh + (uint32_t)(16 * j) * ROWB + ko);
                ldsm4(bl, sKl + (uint32_t)(16 * j) * ROWB + ko);
                mma16816(s[2 * j],     qh[ks], bh + 0);
                mma16816(s[2 * j],     qh[ks], bl + 0);
                mma16816(s[2 * j],     ql[ks], bh + 0);
                mma16816(s[2 * j + 1], qh[ks], bh + 2);
                mma16816(s[2 * j + 1], qh[ks], bl + 2);
                mma16816(s[2 * j + 1], ql[ks], bh + 2);
            }
        }

        // --- online softmax (warp-local) ---
        float mx0 = -1e30f, mx1 = -1e30f;
#pragma unroll
        for (int ni = 0; ni < 8; ni++) {
#pragma unroll
            for (int j = 0; j < 4; j++) s[ni][j] *= SCALE_F;
            mx0 = fmaxf(mx0, fmaxf(s[ni][0], s[ni][1]));
            mx1 = fmaxf(mx1, fmaxf(s[ni][2], s[ni][3]));
        }
        mx0 = fmaxf(mx0, __shfl_xor_sync(0xffffffffu, mx0, 1));
        mx0 = fmaxf(mx0, __shfl_xor_sync(0xffffffffu, mx0, 2));
        mx1 = fmaxf(mx1, __shfl_xor_sync(0xffffffffu, mx1, 1));
        mx1 = fmaxf(mx1, __shfl_xor_sync(0xffffffffu, mx1, 2));
        const float nm0 = fmaxf(m0, mx0);
        const float nm1 = fmaxf(m1, mx1);
        const float al0 = __expf(m0 - nm0);
        const float al1 = __expf(m1 - nm1);
        float sum0 = 0.f, sum1 = 0.f;
#pragma unroll
        for (int ni = 0; ni < 8; ni++) {
            s[ni][0] = __expf(s[ni][0] - nm0);
            s[ni][1] = __expf(s[ni][1] - nm0);
            s[ni][2] = __expf(s[ni][2] - nm1);
            s[ni][3] = __expf(s[ni][3] - nm1);
            sum0 += s[ni][0] + s[ni][1];
            sum1 += s[ni][2] + s[ni][3];
        }
        sum0 += __shfl_xor_sync(0xffffffffu, sum0, 1);
        sum0 += __shfl_xor_sync(0xffffffffu, sum0, 2);
        sum1 += __shfl_xor_sync(0xffffffffu, sum1, 1);
        sum1 += __shfl_xor_sync(0xffffffffu, sum1, 2);
        l0 = l0 * al0 + sum0;
        l1 = l1 * al1 + sum1;
        m0 = nm0;
        m1 = nm1;
#pragma unroll
        for (int ni = 0; ni < 16; ni++) {
            o[ni][0] *= al0; o[ni][1] *= al0;
            o[ni][2] *= al1; o[ni][3] *= al1;
        }

        // --- O += P V (3-pass); P fragments built in registers ---
#pragma unroll
        for (int ks = 0; ks < 4; ks++) {
            uint32_t ph[4], pl[4];
            buildp(ph[0], pl[0], s[2 * ks][0],     s[2 * ks][1]);
            buildp(ph[1], pl[1], s[2 * ks][2],     s[2 * ks][3]);
            buildp(ph[2], pl[2], s[2 * ks + 1][0], s[2 * ks + 1][1]);
            buildp(ph[3], pl[3], s[2 * ks + 1][2], s[2 * ks + 1][3]);
            const uint32_t vro = (uint32_t)(16 * ks) * ROWB;
#pragma unroll
            for (int j = 0; j < 8; j++) {
                uint32_t vh[4], vl[4];
                ldsm4t(vh, sVh + vro + (uint32_t)(32 * j));
                ldsm4t(vl, sVl + vro + (uint32_t)(32 * j));
                mma16816(o[2 * j],     ph, vh + 0);
                mma16816(o[2 * j],     ph, vl + 0);
                mma16816(o[2 * j],     pl, vh + 0);
                mma16816(o[2 * j + 1], ph, vh + 2);
                mma16816(o[2 * j + 1], ph, vl + 2);
                mma16816(o[2 * j + 1], pl, vh + 2);
            }
        }
    }

    // epilogue: normalized O -> fused bf16 hi/lo
    const float inv0 = 1.0f / l0;
    const float inv1 = 1.0f / l1;
    const int row0 = q0 + 16 * wid + g;
    const size_t base0 = ((size_t)(b * QLEN + row0)) * HIDDEN + h * HEAD_DIM;
    const size_t base1 = base0 + (size_t)8 * HIDDEN;
#pragma unroll
    for (int ni = 0; ni < 16; ni++) {
        const int col = 8 * ni + 2 * c;
        uint32_t h0, l0b, h1, l1b;
        buildp(h0, l0b, o[ni][0] * inv0, o[ni][1] * inv0);
        buildp(h1, l1b, o[ni][2] * inv1, o[ni][3] * inv1);
        *(uint32_t*)(Ohi + base0 + col) = h0;
        *(uint32_t*)(Olo + base0 + col) = l0b;
        *(uint32_t*)(Ohi + base1 + col) = h1;
        *(uint32_t*)(Olo + base1 + col) = l1b;
    }
}

// ---------------------------------------------------------------------------
// kernel_launch
// ---------------------------------------------------------------------------
extern "C" void kernel_launch(void* const* d_in, const int* in_sizes, int n_in,
                              void* d_out, int out_size) {
    const float* query = (const float*)d_in[0];
    const float* kv_k  = (const float*)d_in[1];
    const float* kv_v  = (const float*)d_in[2];
    const float* Wq    = (const float*)d_in[3];
    const float* Wo    = (const float*)d_in[4];
    float* out = (float*)d_out;

    __nv_bfloat16 *ahi, *alo, *bhi, *blo, *qhi, *qlo, *khi, *klo, *vhi, *vlo;
    cudaGetSymbolAddress((void**)&ahi, g_Ahi);
    cudaGetSymbolAddress((void**)&alo, g_Alo);
    cudaGetSymbolAddress((void**)&bhi, g_Bhi);
    cudaGetSymbolAddress((void**)&blo, g_Blo);
    cudaGetSymbolAddress((void**)&qhi, g_Qhi);
    cudaGetSymbolAddress((void**)&qlo, g_Qlo);
    cudaGetSymbolAddress((void**)&khi, g_Khi);
    cudaGetSymbolAddress((void**)&klo, g_Klo);
    cudaGetSymbolAddress((void**)&vhi, g_Vhi);
    cudaGetSymbolAddress((void**)&vlo, g_Vlo);

    cudaFuncSetAttribute(gemm_bf16x3, cudaFuncAttributeMaxDynamicSharedMemorySize,
                         GEMM_SMEM);
    cudaFuncSetAttribute(attn_mma, cudaFuncAttributeMaxDynamicSharedMemorySize,
                         ATTN_SMEM);

    const int NA4 = MROWS * HIDDEN / 4;
    const int NW4 = HIDDEN * HIDDEN / 4;
    const int NKV4 = KVLEN * HIDDEN / 4;
    dim3 gemm_grid(HIDDEN / 128, MROWS / 128);  // (16, 64)

    // Q projection (epilogue writes bf16 hi/lo directly)
    split_bf16<<<2048, 256>>>((const float4*)query, (uint2*)ahi, (uint2*)alo, NA4);
    split_bf16<<<1024, 256>>>((const float4*)Wq, (uint2*)bhi, (uint2*)blo, NW4);
    gemm_bf16x3<<<gemm_grid, 256, GEMM_SMEM>>>(ahi, alo, bhi, blo,
                                               qhi, qlo, nullptr);

    // KV splits
    split_bf16<<<1024, 256>>>((const float4*)kv_k, (uint2*)khi, (uint2*)klo, NKV4);
    split_bf16<<<1024, 256>>>((const float4*)kv_v, (uint2*)vhi, (uint2*)vlo, NKV4);

    // Attention (epilogue writes bf16 hi/lo into A buffers)
    dim3 attn_grid(QLEN / 128, BATCH * HEADS);  // (8, 128)
    attn_mma<<<attn_grid, 256, ATTN_SMEM>>>(qhi, qlo, khi, klo, vhi, vlo, ahi, alo);

    // Output projection (fp32 out)
    split_bf16<<<1024, 256>>>((const float4*)Wo, (uint2*)bhi, (uint2*)blo, NW4);
    gemm_bf16x3<<<gemm_grid, 256, GEMM_SMEM>>>(ahi, alo, bhi, blo,
                                               nullptr, nullptr, out);
}

// round 15
// speedup vs baseline: 4.1295x; 1.4280x over previous
#include <cuda_runtime.h>
#include <cuda_fp16.h>
#include <stdint.h>
#include <math.h>

#define HIDDEN 2048
#define HEADS 16
#define HEAD_DIM 128
#define BATCH 8
#define QLEN 1024
#define KVLEN 4096
#define MROWS (BATCH * QLEN) /* 8192 */

#define SCALE_F 0.08838834764831845f /* 1/sqrt(128) */

// ---------------------------------------------------------------------------
// Static scratch (alloc-free rule). A-side operands carry hi/lo; B-side only hi.
// ---------------------------------------------------------------------------
__device__ __half g_Ahi[(size_t)MROWS * HIDDEN];
__device__ __half g_Alo[(size_t)MROWS * HIDDEN];
__device__ __half g_Bh[(size_t)HIDDEN * HIDDEN];
__device__ __half g_Qhi[(size_t)MROWS * HIDDEN];
__device__ __half g_Qlo[(size_t)MROWS * HIDDEN];
__device__ __half g_Kh[(size_t)KVLEN * HIDDEN];
__device__ __half g_Vh[(size_t)KVLEN * HIDDEN];

extern __shared__ __align__(16) char dyn_smem[];

// ---------------------------------------------------------------------------
// PTX helpers
// ---------------------------------------------------------------------------
__device__ __forceinline__ uint32_t smem_u32(const void* p) {
    uint32_t a;
    asm("{ .reg .u64 t; cvta.to.shared.u64 t, %1; cvt.u32.u64 %0, t; }"
        : "=r"(a) : "l"(p));
    return a;
}

__device__ __forceinline__ void cp16(uint32_t dst, const void* src) {
    asm volatile("cp.async.cg.shared.global [%0], [%1], 16;" :: "r"(dst), "l"(src));
}
#define CP_COMMIT() asm volatile("cp.async.commit_group;" ::: "memory")

__device__ __forceinline__ void ldsm4(uint32_t* r, uint32_t addr) {
    asm volatile("ldmatrix.sync.aligned.m8n8.x4.shared.b16 {%0,%1,%2,%3}, [%4];"
                 : "=r"(r[0]), "=r"(r[1]), "=r"(r[2]), "=r"(r[3]) : "r"(addr));
}

__device__ __forceinline__ void ldsm4t(uint32_t* r, uint32_t addr) {
    asm volatile("ldmatrix.sync.aligned.m8n8.x4.trans.shared.b16 {%0,%1,%2,%3}, [%4];"
                 : "=r"(r[0]), "=r"(r[1]), "=r"(r[2]), "=r"(r[3]) : "r"(addr));
}

__device__ __forceinline__ void mma16816(float* d, const uint32_t* a,
                                         const uint32_t* b) {
    asm volatile(
        "mma.sync.aligned.m16n8k16.row.col.f32.f16.f16.f32 "
        "{%0,%1,%2,%3}, {%4,%5,%6,%7}, {%8,%9}, {%0,%1,%2,%3};"
        : "+f"(d[0]), "+f"(d[1]), "+f"(d[2]), "+f"(d[3])
        : "r"(a[0]), "r"(a[1]), "r"(a[2]), "r"(a[3]), "r"(b[0]), "r"(b[1]));
}

// pack two fp32 -> half2 (a in low, b in high)
__device__ __forceinline__ uint32_t packh(float a, float b) {
    __half2 h = __floats2half2_rn(a, b);
    return *(uint32_t*)&h;
}

// build hi/lo half2 pair from two fp32 values (a = k-even, b = k-odd)
__device__ __forceinline__ void buildp(uint32_t& ph, uint32_t& pl, float a, float b) {
    float ra = a - __half2float(__float2half_rn(a));
    float rb = b - __half2float(__float2half_rn(b));
    ph = packh(a, b);
    pl = packh(ra, rb);
}

// ---------------------------------------------------------------------------
// fp32 -> (fp16 hi, fp16 lo) split, float4 vectorized (A-side operands)
// ---------------------------------------------------------------------------
__global__ void split_fp16(const float4* __restrict__ x,
                           uint2* __restrict__ hi, uint2* __restrict__ lo, int n4) {
    int i = blockIdx.x * blockDim.x + threadIdx.x;
    int stride = gridDim.x * blockDim.x;
    for (; i < n4; i += stride) {
        float4 v = x[i];
        uint32_t h0, l0, h1, l1;
        buildp(h0, l0, v.x, v.y);
        buildp(h1, l1, v.z, v.w);
        hi[i] = make_uint2(h0, h1);
        lo[i] = make_uint2(l0, l1);
    }
}

// fp32 -> fp16 convert only (B-side operands)
__global__ void conv_fp16(const float4* __restrict__ x,
                          uint2* __restrict__ hi, int n4) {
    int i = blockIdx.x * blockDim.x + threadIdx.x;
    int stride = gridDim.x * blockDim.x;
    for (; i < n4; i += stride) {
        float4 v = x[i];
        hi[i] = make_uint2(packh(v.x, v.y), packh(v.z, v.w));
    }
}

// ---------------------------------------------------------------------------
// fp16 2-pass GEMM (NT) via mma.sync m16n8k16: C = (Ahi+Alo) Bh^T, fp32 accum.
// CTA 128x128, BK=64 (32 chunks), 3-stage cp.async, one sync per chunk.
// Stage: Ahi | Alo | Bh, each 128 rows x 144B.
// Output: fp32 (Cf) or fused fp16 hi/lo split (Chi/Clo) when Cf==nullptr.
// ---------------------------------------------------------------------------
#define BK 64
#define NCHUNKS (HIDDEN / BK) /* 32 */
#define GROWB 144
#define GTILE_B (128 * GROWB)    /* 18432 */
#define GSTAGE_B (3 * GTILE_B)   /* 55296 */
#define GEMM_SMEM (3 * GSTAGE_B) /* 165888 */

__global__ __launch_bounds__(256, 1) void gemm_f16x2(
    const __half* __restrict__ Ahi, const __half* __restrict__ Alo,
    const __half* __restrict__ Bh,
    __half* __restrict__ Chi, __half* __restrict__ Clo,
    float* __restrict__ Cf) {
    const uint32_t sbase = smem_u32(dyn_smem);
    const int tid = threadIdx.x;
    const int wid = tid >> 5;
    const int lane = tid & 31;
    const int warp_m = wid >> 2;
    const int warp_n = wid & 3;
    const int bm = blockIdx.y << 7;
    const int bn = blockIdx.x << 7;

    const __half* gAh = Ahi + (size_t)bm * HIDDEN;
    const __half* gAl = Alo + (size_t)bm * HIDDEN;
    const __half* gB  = Bh  + (size_t)bn * HIDDEN;

    auto load_chunk = [&](int c) {
        const uint32_t stg = sbase + (uint32_t)(c % 3) * GSTAGE_B;
        const int k0 = c * BK;
#pragma unroll
        for (int i = 0; i < 4; i++) {
            const int slot = tid + i * 256;
            const int r = slot >> 3;
            const int c16 = slot & 7;
            const uint32_t so = (uint32_t)r * GROWB + (uint32_t)c16 * 16u;
            const size_t go = (size_t)r * HIDDEN + k0 + c16 * 8;
            cp16(stg + 0 * GTILE_B + so, gAh + go);
            cp16(stg + 1 * GTILE_B + so, gAl + go);
            cp16(stg + 2 * GTILE_B + so, gB + go);
        }
        CP_COMMIT();
    };

    float acc[4][4][4];
#pragma unroll
    for (int mi = 0; mi < 4; mi++)
#pragma unroll
        for (int ni = 0; ni < 4; ni++)
#pragma unroll
            for (int j = 0; j < 4; j++) acc[mi][ni][j] = 0.f;

    const uint32_t a_off = (uint32_t)(lane & 15) * GROWB + (uint32_t)((lane >> 4) << 4);
    const uint32_t b_row = (uint32_t)((lane & 7) + ((lane >> 4) << 3));
    const uint32_t b_off = b_row * GROWB + (uint32_t)(((lane >> 3) & 1) << 4);

    load_chunk(0);
    load_chunk(1);

    for (int c = 0; c < NCHUNKS; c++) {
        if (c == NCHUNKS - 1)
            asm volatile("cp.async.wait_group 0;" ::: "memory");
        else
            asm volatile("cp.async.wait_group 1;" ::: "memory");
        __syncthreads();
        if (c + 2 < NCHUNKS) load_chunk(c + 2);

        const uint32_t stg = sbase + (uint32_t)(c % 3) * GSTAGE_B;
        const uint32_t sAh = stg + 0 * GTILE_B + (uint32_t)(warp_m * 64) * GROWB + a_off;
        const uint32_t sAl = stg + 1 * GTILE_B + (uint32_t)(warp_m * 64) * GROWB + a_off;
        const uint32_t sB  = stg + 2 * GTILE_B + (uint32_t)(warp_n * 32) * GROWB + b_off;

#pragma unroll
        for (int ks = 0; ks < 4; ks++) {
            const uint32_t ko = (uint32_t)(ks * 32);
            uint32_t ah[4][4], al[4][4], bh[2][4];
#pragma unroll
            for (int mi = 0; mi < 4; mi++) {
                ldsm4(ah[mi], sAh + (uint32_t)(mi * 16) * GROWB + ko);
                ldsm4(al[mi], sAl + (uint32_t)(mi * 16) * GROWB + ko);
            }
#pragma unroll
            for (int bi = 0; bi < 2; bi++)
                ldsm4(bh[bi], sB + (uint32_t)(bi * 16) * GROWB + ko);
#pragma unroll
            for (int mi = 0; mi < 4; mi++) {
#pragma unroll
                for (int ni = 0; ni < 4; ni++) {
                    const uint32_t* bhf = &bh[ni >> 1][(ni & 1) * 2];
                    mma16816(acc[mi][ni], ah[mi], bhf);
                    mma16816(acc[mi][ni], al[mi], bhf);
                }
            }
        }
    }

    const int er = lane >> 2;
    const int ec = (lane & 3) * 2;
    if (Cf) {
#pragma unroll
        for (int mi = 0; mi < 4; mi++) {
            const int row = bm + warp_m * 64 + mi * 16 + er;
#pragma unroll
            for (int ni = 0; ni < 4; ni++) {
                const int col = bn + warp_n * 32 + ni * 8 + ec;
                *(float2*)(Cf + (size_t)row * HIDDEN + col) =
                    make_float2(acc[mi][ni][0], acc[mi][ni][1]);
                *(float2*)(Cf + (size_t)(row + 8) * HIDDEN + col) =
                    make_float2(acc[mi][ni][2], acc[mi][ni][3]);
            }
        }
    } else {
#pragma unroll
        for (int mi = 0; mi < 4; mi++) {
            const int row = bm + warp_m * 64 + mi * 16 + er;
#pragma unroll
            for (int ni = 0; ni < 4; ni++) {
                const int col = bn + warp_n * 32 + ni * 8 + ec;
                uint32_t h0, l0, h1, l1;
                buildp(h0, l0, acc[mi][ni][0], acc[mi][ni][1]);
                buildp(h1, l1, acc[mi][ni][2], acc[mi][ni][3]);
                *(uint32_t*)(Chi + (size_t)row * HIDDEN + col) = h0;
                *(uint32_t*)(Clo + (size_t)row * HIDDEN + col) = l0;
                *(uint32_t*)(Chi + (size_t)(row + 8) * HIDDEN + col) = h1;
                *(uint32_t*)(Clo + (size_t)(row + 8) * HIDDEN + col) = l1;
            }
        }
    }
}

// ---------------------------------------------------------------------------
// HMMA flash attention, fp16 2-pass (Q and P split hi/lo; K,V rounded fp16).
// BQ=128, BK=64, 256 threads, warp grid 8(M)x1(N). Q frags persistent in regs.
// 3-stage KV pipeline, one __syncthreads per chunk.
// Stage: {Kh, Vh} x 64 rows x 272B = 34816 B; 3 stages = 104448 B.
// ---------------------------------------------------------------------------
#define ROWB 272
#define QT_B (128 * ROWB)          /* 34816 */
#define KT_B (64 * ROWB)           /* 17408 */
#define STG_B (2 * KT_B)           /* 34816 */
#define ATTN_SMEM (3 * STG_B)      /* 104448 */

__global__ __launch_bounds__(256, 1) void attn_mma(
    const __half* __restrict__ Qhi, const __half* __restrict__ Qlo,
    const __half* __restrict__ Kh, const __half* __restrict__ Vh,
    __half* __restrict__ Ohi, __half* __restrict__ Olo) {
    const uint32_t sb = smem_u32(dyn_smem);
    const int tid = threadIdx.x;
    const int wid = tid >> 5;
    const int lane = tid & 31;
    const int h = blockIdx.y & 15;
    const int b = blockIdx.y >> 4;
    const int q0 = blockIdx.x << 7;
    const int g = lane >> 2;
    const int c = lane & 3;

    // --- stage Q hi/lo (fits in stages 0+1; recycled after frag load) ---
    {
        const size_t qg = ((size_t)(b * QLEN + q0)) * HIDDEN + h * HEAD_DIM;
#pragma unroll
        for (int i = 0; i < 8; i++) {
            int slot = tid + i * 256;
            int r = slot >> 4, c16 = slot & 15;
            uint32_t so = (uint32_t)r * ROWB + (uint32_t)c16 * 16u;
            size_t go = qg + (size_t)r * HIDDEN + c16 * 8;
            cp16(sb + so, Qhi + go);
            cp16(sb + QT_B + so, Qlo + go);
        }
        CP_COMMIT();
    }

    const uint32_t a_off = (uint32_t)(lane & 15) * ROWB + (uint32_t)((lane >> 4) << 4);
    const uint32_t b_row = (uint32_t)((lane & 7) + ((lane >> 4) << 3));
    const uint32_t b_off = b_row * ROWB + (uint32_t)(((lane >> 3) & 1) << 4);
    const uint32_t v_row = (uint32_t)((lane & 7) + (((lane >> 3) & 1) << 3));
    const uint32_t v_off = v_row * ROWB + (uint32_t)(((lane >> 4) & 1) << 4);

    // --- load Q fragments into persistent registers ---
    uint32_t qh[8][4], ql[8][4];
    {
        asm volatile("cp.async.wait_group 0;" ::: "memory");
        __syncthreads();
        const uint32_t aQh = sb + (uint32_t)(16 * wid) * ROWB + a_off;
        const uint32_t aQl = aQh + QT_B;
#pragma unroll
        for (int ks = 0; ks < 8; ks++) {
            ldsm4(qh[ks], aQh + (uint32_t)(ks * 32));
            ldsm4(ql[ks], aQl + (uint32_t)(ks * 32));
        }
        __syncthreads();  // Q region may now be recycled as KV stages
    }

    auto load_kv = [&](int cc) {
        const uint32_t stg = sb + (uint32_t)(cc % 3) * STG_B;
        const int kb = cc << 6;
#pragma unroll
        for (int i = 0; i < 4; i++) {
            int slot = tid + i * 256;
            int r = slot >> 4, c16 = slot & 15;
            uint32_t so = (uint32_t)r * ROWB + (uint32_t)c16 * 16u;
            size_t go = (size_t)(kb + r) * HIDDEN + h * HEAD_DIM + c16 * 8;
            cp16(stg + 0 * KT_B + so, Kh + go);
            cp16(stg + 1 * KT_B + so, Vh + go);
        }
        CP_COMMIT();
    };
    load_kv(0);
    load_kv(1);

    float m0 = -1e30f, m1 = -1e30f, l0 = 0.f, l1 = 0.f;
    float o[16][4];
#pragma unroll
    for (int ni = 0; ni < 16; ni++)
#pragma unroll
        for (int j = 0; j < 4; j++) o[ni][j] = 0.f;

    for (int ch = 0; ch < 64; ch++) {
        if (ch == 63)
            asm volatile("cp.async.wait_group 0;" ::: "memory");
        else
            asm volatile("cp.async.wait_group 1;" ::: "memory");
        __syncthreads();
        if (ch + 2 < 64) load_kv(ch + 2);

        const uint32_t stg = sb + (uint32_t)(ch % 3) * STG_B;
        const uint32_t sK = stg + 0 * KT_B + b_off;
        const uint32_t sV = stg + 1 * KT_B + v_off;

        // --- S = Q K^T (2-pass: Qhi·K + Qlo·K) ---
        float s[8][4];
#pragma unroll
        for (int ni = 0; ni < 8; ni++)
#pragma unroll
            for (int j = 0; j < 4; j++) s[ni][j] = 0.f;

#pragma unroll
        for (int ks = 0; ks < 8; ks++) {
            const uint32_t ko = (uint32_t)(ks * 32);
#pragma unroll
            for (int j = 0; j < 4; j++) {
                uint32_t bh[4];
                ldsm4(bh, sK + (uint32_t)(16 * j) * ROWB + ko);
                mma16816(s[2 * j],     qh[ks], bh + 0);
                mma16816(s[2 * j],     ql[ks], bh + 0);
                mma16816(s[2 * j + 1], qh[ks], bh + 2);
                mma16816(s[2 * j + 1], ql[ks], bh + 2);
            }
        }

        // --- online softmax (warp-local) ---
        float mx0 = -1e30f, mx1 = -1e30f;
#pragma unroll
        for (int ni = 0; ni < 8; ni++) {
#pragma unroll
            for (int j = 0; j < 4; j++) s[ni][j] *= SCALE_F;
            mx0 = fmaxf(mx0, fmaxf(s[ni][0], s[ni][1]));
            mx1 = fmaxf(mx1, fmaxf(s[ni][2], s[ni][3]));
        }
        mx0 = fmaxf(mx0, __shfl_xor_sync(0xffffffffu, mx0, 1));
        mx0 = fmaxf(mx0, __shfl_xor_sync(0xffffffffu, mx0, 2));
        mx1 = fmaxf(mx1, __shfl_xor_sync(0xffffffffu, mx1, 1));
        mx1 = fmaxf(mx1, __shfl_xor_sync(0xffffffffu, mx1, 2));
        const float nm0 = fmaxf(m0, mx0);
        const float nm1 = fmaxf(m1, mx1);
        const float al0 = __expf(m0 - nm0);
        const float al1 = __expf(m1 - nm1);
        float sum0 = 0.f, sum1 = 0.f;
#pragma unroll
        for (int ni = 0; ni < 8; ni++) {
            s[ni][0] = __expf(s[ni][0] - nm0);
            s[ni][1] = __expf(s[ni][1] - nm0);
            s[ni][2] = __expf(s[ni][2] - nm1);
            s[ni][3] = __expf(s[ni][3] - nm1);
            sum0 += s[ni][0] + s[ni][1];
            sum1 += s[ni][2] + s[ni][3];
        }
        sum0 += __shfl_xor_sync(0xffffffffu, sum0, 1);
        sum0 += __shfl_xor_sync(0xffffffffu, sum0, 2);
        sum1 += __shfl_xor_sync(0xffffffffu, sum1, 1);
        sum1 += __shfl_xor_sync(0xffffffffu, sum1, 2);
        l0 = l0 * al0 + sum0;
        l1 = l1 * al1 + sum1;
        m0 = nm0;
        m1 = nm1;
#pragma unroll
        for (int ni = 0; ni < 16; ni++) {
            o[ni][0] *= al0; o[ni][1] *= al0;
            o[ni][2] *= al1; o[ni][3] *= al1;
        }

        // --- O += P V (2-pass: Phi·V + Plo·V) ---
#pragma unroll
        for (int ks = 0; ks < 4; ks++) {
            uint32_t ph[4], pl[4];
            buildp(ph[0], pl[0], s[2 * ks][0],     s[2 * ks][1]);
            buildp(ph[1], pl[1], s[2 * ks][2],     s[2 * ks][3]);
            buildp(ph[2], pl[2], s[2 * ks + 1][0], s[2 * ks + 1][1]);
            buildp(ph[3], pl[3], s[2 * ks + 1][2], s[2 * ks + 1][3]);
            const uint32_t vro = (uint32_t)(16 * ks) * ROWB;
#pragma unroll
            for (int j = 0; j < 8; j++) {
                uint32_t vh[4];
                ldsm4t(vh, sV + vro + (uint32_t)(32 * j));
                mma16816(o[2 * j],     ph, vh + 0);
                mma16816(o[2 * j],     pl, vh + 0);
                mma16816(o[2 * j + 1], ph, vh + 2);
                mma16816(o[2 * j + 1], pl, vh + 2);
            }
        }
    }

    // epilogue: normalized O -> fused fp16 hi/lo
    const float inv0 = 1.0f / l0;
    const float inv1 = 1.0f / l1;
    const int row0 = q0 + 16 * wid + g;
    const size_t base0 = ((size_t)(b * QLEN + row0)) * HIDDEN + h * HEAD_DIM;
    const size_t base1 = base0 + (size_t)8 * HIDDEN;
#pragma unroll
    for (int ni = 0; ni < 16; ni++) {
        const int col = 8 * ni + 2 * c;
        uint32_t h0, l0b, h1, l1b;
        buildp(h0, l0b, o[ni][0] * inv0, o[ni][1] * inv0);
        buildp(h1, l1b, o[ni][2] * inv1, o[ni][3] * inv1);
        *(uint32_t*)(Ohi + base0 + col) = h0;
        *(uint32_t*)(Olo + base0 + col) = l0b;
        *(uint32_t*)(Ohi + base1 + col) = h1;
        *(uint32_t*)(Olo + base1 + col) = l1b;
    }
}

// ---------------------------------------------------------------------------
// kernel_launch
// ---------------------------------------------------------------------------
extern "C" void kernel_launch(void* const* d_in, const int* in_sizes, int n_in,
                              void* d_out, int out_size) {
    const float* query = (const float*)d_in[0];
    const float* kv_k  = (const float*)d_in[1];
    const float* kv_v  = (const float*)d_in[2];
    const float* Wq    = (const float*)d_in[3];
    const float* Wo    = (const float*)d_in[4];
    float* out = (float*)d_out;

    __half *ahi, *alo, *bh, *qhi, *qlo, *kh, *vh;
    cudaGetSymbolAddress((void**)&ahi, g_Ahi);
    cudaGetSymbolAddress((void**)&alo, g_Alo);
    cudaGetSymbolAddress((void**)&bh, g_Bh);
    cudaGetSymbolAddress((void**)&qhi, g_Qhi);
    cudaGetSymbolAddress((void**)&qlo, g_Qlo);
    cudaGetSymbolAddress((void**)&kh, g_Kh);
    cudaGetSymbolAddress((void**)&vh, g_Vh);

    cudaFuncSetAttribute(gemm_f16x2, cudaFuncAttributeMaxDynamicSharedMemorySize,
                         GEMM_SMEM);
    cudaFuncSetAttribute(attn_mma, cudaFuncAttributeMaxDynamicSharedMemorySize,
                         ATTN_SMEM);

    const int NA4 = MROWS * HIDDEN / 4;
    const int NW4 = HIDDEN * HIDDEN / 4;
    const int NKV4 = KVLEN * HIDDEN / 4;
    dim3 gemm_grid(HIDDEN / 128, MROWS / 128);  // (16, 64)

    // Q projection: query split (A-side), Wq rounded (B-side)
    split_fp16<<<2048, 256>>>((const float4*)query, (uint2*)ahi, (uint2*)alo, NA4);
    conv_fp16<<<1024, 256>>>((const float4*)Wq, (uint2*)bh, NW4);
    gemm_f16x2<<<gemm_grid, 256, GEMM_SMEM>>>(ahi, alo, bh, qhi, qlo, nullptr);

    // KV converts (B-side only)
    conv_fp16<<<1024, 256>>>((const float4*)kv_k, (uint2*)kh, NKV4);
    conv_fp16<<<1024, 256>>>((const float4*)kv_v, (uint2*)vh, NKV4);

    // Attention (epilogue writes fp16 hi/lo into A buffers)
    dim3 attn_grid(QLEN / 128, BATCH * HEADS);  // (8, 128)
    attn_mma<<<attn_grid, 256, ATTN_SMEM>>>(qhi, qlo, kh, vh, ahi, alo);

    // Output projection (fp32 out)
    conv_fp16<<<1024, 256>>>((const float4*)Wo, (uint2*)bh, NW4);
    gemm_f16x2<<<gemm_grid, 256, GEMM_SMEM>>>(ahi, alo, bh,
                                              nullptr, nullptr, out);
}

// round 17
// speedup vs baseline: 5.3553x; 1.2968x over previous
#include <cuda_runtime.h>
#include <cuda_fp16.h>
#include <stdint.h>
#include <math.h>

#define HIDDEN 2048
#define HEADS 16
#define HEAD_DIM 128
#define BATCH 8
#define QLEN 1024
#define KVLEN 4096
#define MROWS (BATCH * QLEN) /* 8192 */

#define SCALE_F 0.08838834764831845f /* 1/sqrt(128) */

// ---------------------------------------------------------------------------
// Static scratch (alloc-free rule)
// ---------------------------------------------------------------------------
__device__ __half g_Ahi[(size_t)MROWS * HIDDEN];
__device__ __half g_Alo[(size_t)MROWS * HIDDEN];
__device__ __half g_Bh[(size_t)HIDDEN * HIDDEN];
__device__ __half g_Qh[(size_t)MROWS * HIDDEN];
__device__ __half g_Kh[(size_t)KVLEN * HIDDEN];
__device__ __half g_Vh[(size_t)KVLEN * HIDDEN];

extern __shared__ __align__(16) char dyn_smem[];

// ---------------------------------------------------------------------------
// PTX helpers
// ---------------------------------------------------------------------------
__device__ __forceinline__ uint32_t smem_u32(const void* p) {
    uint32_t a;
    asm("{ .reg .u64 t; cvta.to.shared.u64 t, %1; cvt.u32.u64 %0, t; }"
        : "=r"(a) : "l"(p));
    return a;
}

__device__ __forceinline__ void cp16(uint32_t dst, const void* src) {
    asm volatile("cp.async.cg.shared.global [%0], [%1], 16;" :: "r"(dst), "l"(src));
}
#define CP_COMMIT() asm volatile("cp.async.commit_group;" ::: "memory")

__device__ __forceinline__ void ldsm4(uint32_t* r, uint32_t addr) {
    asm volatile("ldmatrix.sync.aligned.m8n8.x4.shared.b16 {%0,%1,%2,%3}, [%4];"
                 : "=r"(r[0]), "=r"(r[1]), "=r"(r[2]), "=r"(r[3]) : "r"(addr));
}

__device__ __forceinline__ void ldsm4t(uint32_t* r, uint32_t addr) {
    asm volatile("ldmatrix.sync.aligned.m8n8.x4.trans.shared.b16 {%0,%1,%2,%3}, [%4];"
                 : "=r"(r[0]), "=r"(r[1]), "=r"(r[2]), "=r"(r[3]) : "r"(addr));
}

__device__ __forceinline__ void mma16816(float* d, const uint32_t* a,
                                         const uint32_t* b) {
    asm volatile(
        "mma.sync.aligned.m16n8k16.row.col.f32.f16.f16.f32 "
        "{%0,%1,%2,%3}, {%4,%5,%6,%7}, {%8,%9}, {%0,%1,%2,%3};"
        : "+f"(d[0]), "+f"(d[1]), "+f"(d[2]), "+f"(d[3])
        : "r"(a[0]), "r"(a[1]), "r"(a[2]), "r"(a[3]), "r"(b[0]), "r"(b[1]));
}

// pack two fp32 -> half2 (a in low, b in high)
__device__ __forceinline__ uint32_t packh(float a, float b) {
    __half2 h = __floats2half2_rn(a, b);
    return *(uint32_t*)&h;
}

// build hi/lo half2 pair from two fp32 values (a = k-even, b = k-odd)
__device__ __forceinline__ void buildp(uint32_t& ph, uint32_t& pl, float a, float b) {
    float ra = a - __half2float(__float2half_rn(a));
    float rb = b - __half2float(__float2half_rn(b));
    ph = packh(a, b);
    pl = packh(ra, rb);
}

// ---------------------------------------------------------------------------
// fp32 -> (fp16 hi, fp16 lo) split (A-side operands of projections)
// ---------------------------------------------------------------------------
__global__ void split_fp16(const float4* __restrict__ x,
                           uint2* __restrict__ hi, uint2* __restrict__ lo, int n4) {
    int i = blockIdx.x * blockDim.x + threadIdx.x;
    int stride = gridDim.x * blockDim.x;
    for (; i < n4; i += stride) {
        float4 v = x[i];
        uint32_t h0, l0, h1, l1;
        buildp(h0, l0, v.x, v.y);
        buildp(h1, l1, v.z, v.w);
        hi[i] = make_uint2(h0, h1);
        lo[i] = make_uint2(l0, l1);
    }
}

// fp32 -> fp16 convert only (B-side operands; K, V, weights)
__global__ void conv_fp16(const float4* __restrict__ x,
                          uint2* __restrict__ hi, int n4) {
    int i = blockIdx.x * blockDim.x + threadIdx.x;
    int stride = gridDim.x * blockDim.x;
    for (; i < n4; i += stride) {
        float4 v = x[i];
        hi[i] = make_uint2(packh(v.x, v.y), packh(v.z, v.w));
    }
}

// ---------------------------------------------------------------------------
// fp16 2-pass GEMM (NT) via mma.sync m16n8k16: C = (Ahi+Alo) Bh^T, fp32 accum.
// Output modes: Cf!=null -> fp32; Clo!=null -> fp16 hi/lo; else fp16 hi only.
// ---------------------------------------------------------------------------
#define BK 64
#define NCHUNKS (HIDDEN / BK) /* 32 */
#define GROWB 144
#define GTILE_B (128 * GROWB)    /* 18432 */
#define GSTAGE_B (3 * GTILE_B)   /* 55296 */
#define GEMM_SMEM (3 * GSTAGE_B) /* 165888 */

__global__ __launch_bounds__(256, 1) void gemm_f16x2(
    const __half* __restrict__ Ahi, const __half* __restrict__ Alo,
    const __half* __restrict__ Bh,
    __half* __restrict__ Chi, __half* __restrict__ Clo,
    float* __restrict__ Cf) {
    const uint32_t sbase = smem_u32(dyn_smem);
    const int tid = threadIdx.x;
    const int wid = tid >> 5;
    const int lane = tid & 31;
    const int warp_m = wid >> 2;
    const int warp_n = wid & 3;
    const int bm = blockIdx.y << 7;
    const int bn = blockIdx.x << 7;

    const __half* gAh = Ahi + (size_t)bm * HIDDEN;
    const __half* gAl = Alo + (size_t)bm * HIDDEN;
    const __half* gB  = Bh  + (size_t)bn * HIDDEN;

    auto load_chunk = [&](int c) {
        const uint32_t stg = sbase + (uint32_t)(c % 3) * GSTAGE_B;
        const int k0 = c * BK;
#pragma unroll
        for (int i = 0; i < 4; i++) {
            const int slot = tid + i * 256;
            const int r = slot >> 3;
            const int c16 = slot & 7;
            const uint32_t so = (uint32_t)r * GROWB + (uint32_t)c16 * 16u;
            const size_t go = (size_t)r * HIDDEN + k0 + c16 * 8;
            cp16(stg + 0 * GTILE_B + so, gAh + go);
            cp16(stg + 1 * GTILE_B + so, gAl + go);
            cp16(stg + 2 * GTILE_B + so, gB + go);
        }
        CP_COMMIT();
    };

    float acc[4][4][4];
#pragma unroll
    for (int mi = 0; mi < 4; mi++)
#pragma unroll
        for (int ni = 0; ni < 4; ni++)
#pragma unroll
            for (int j = 0; j < 4; j++) acc[mi][ni][j] = 0.f;

    const uint32_t a_off = (uint32_t)(lane & 15) * GROWB + (uint32_t)((lane >> 4) << 4);
    const uint32_t b_row = (uint32_t)((lane & 7) + ((lane >> 4) << 3));
    const uint32_t b_off = b_row * GROWB + (uint32_t)(((lane >> 3) & 1) << 4);

    load_chunk(0);
    load_chunk(1);

    for (int c = 0; c < NCHUNKS; c++) {
        if (c == NCHUNKS - 1)
            asm volatile("cp.async.wait_group 0;" ::: "memory");
        else
            asm volatile("cp.async.wait_group 1;" ::: "memory");
        __syncthreads();
        if (c + 2 < NCHUNKS) load_chunk(c + 2);

        const uint32_t stg = sbase + (uint32_t)(c % 3) * GSTAGE_B;
        const uint32_t sAh = stg + 0 * GTILE_B + (uint32_t)(warp_m * 64) * GROWB + a_off;
        const uint32_t sAl = stg + 1 * GTILE_B + (uint32_t)(warp_m * 64) * GROWB + a_off;
        const uint32_t sB  = stg + 2 * GTILE_B + (uint32_t)(warp_n * 32) * GROWB + b_off;

#pragma unroll
        for (int ks = 0; ks < 4; ks++) {
            const uint32_t ko = (uint32_t)(ks * 32);
            uint32_t ah[4][4], al[4][4], bh[2][4];
#pragma unroll
            for (int mi = 0; mi < 4; mi++) {
                ldsm4(ah[mi], sAh + (uint32_t)(mi * 16) * GROWB + ko);
                ldsm4(al[mi], sAl + (uint32_t)(mi * 16) * GROWB + ko);
            }
#pragma unroll
            for (int bi = 0; bi < 2; bi++)
                ldsm4(bh[bi], sB + (uint32_t)(bi * 16) * GROWB + ko);
#pragma unroll
            for (int mi = 0; mi < 4; mi++) {
#pragma unroll
                for (int ni = 0; ni < 4; ni++) {
                    const uint32_t* bhf = &bh[ni >> 1][(ni & 1) * 2];
                    mma16816(acc[mi][ni], ah[mi], bhf);
                    mma16816(acc[mi][ni], al[mi], bhf);
                }
            }
        }
    }

    const int er = lane >> 2;
    const int ec = (lane & 3) * 2;
    if (Cf) {
#pragma unroll
        for (int mi = 0; mi < 4; mi++) {
            const int row = bm + warp_m * 64 + mi * 16 + er;
#pragma unroll
            for (int ni = 0; ni < 4; ni++) {
                const int col = bn + warp_n * 32 + ni * 8 + ec;
                *(float2*)(Cf + (size_t)row * HIDDEN + col) =
                    make_float2(acc[mi][ni][0], acc[mi][ni][1]);
                *(float2*)(Cf + (size_t)(row + 8) * HIDDEN + col) =
                    make_float2(acc[mi][ni][2], acc[mi][ni][3]);
            }
        }
    } else if (Clo) {
#pragma unroll
        for (int mi = 0; mi < 4; mi++) {
            const int row = bm + warp_m * 64 + mi * 16 + er;
#pragma unroll
            for (int ni = 0; ni < 4; ni++) {
                const int col = bn + warp_n * 32 + ni * 8 + ec;
                uint32_t h0, l0, h1, l1;
                buildp(h0, l0, acc[mi][ni][0], acc[mi][ni][1]);
                buildp(h1, l1, acc[mi][ni][2], acc[mi][ni][3]);
                *(uint32_t*)(Chi + (size_t)row * HIDDEN + col) = h0;
                *(uint32_t*)(Clo + (size_t)row * HIDDEN + col) = l0;
                *(uint32_t*)(Chi + (size_t)(row + 8) * HIDDEN + col) = h1;
                *(uint32_t*)(Clo + (size_t)(row + 8) * HIDDEN + col) = l1;
            }
        }
    } else {
#pragma unroll
        for (int mi = 0; mi < 4; mi++) {
            const int row = bm + warp_m * 64 + mi * 16 + er;
#pragma unroll
            for (int ni = 0; ni < 4; ni++) {
                const int col = bn + warp_n * 32 + ni * 8 + ec;
                *(uint32_t*)(Chi + (size_t)row * HIDDEN + col) =
                    packh(acc[mi][ni][0], acc[mi][ni][1]);
                *(uint32_t*)(Chi + (size_t)(row + 8) * HIDDEN + col) =
                    packh(acc[mi][ni][2], acc[mi][ni][3]);
            }
        }
    }
}

// ---------------------------------------------------------------------------
// HMMA flash attention, pure fp16 operands (Q,K,V,P rounded), fp32 accum.
// BQ=128, BK=64, 256 threads, warp grid 8(M)x1(N). Q frags persistent in regs.
// 3-stage KV pipeline, one __syncthreads per chunk.
// Stage: {Kh, Vh} x 64 rows x 272B = 34816 B; 3 stages = 104448 B.
// Epilogue writes O as fp16 hi/lo (A-side of the 2-pass O-projection).
// ---------------------------------------------------------------------------
#define ROWB 272
#define QT_B (128 * ROWB)          /* 34816 */
#define KT_B (64 * ROWB)           /* 17408 */
#define STG_B (2 * KT_B)           /* 34816 */
#define ATTN_SMEM (3 * STG_B)      /* 104448 */

__global__ __launch_bounds__(256, 1) void attn_mma(
    const __half* __restrict__ Qh,
    const __half* __restrict__ Kh, const __half* __restrict__ Vh,
    __half* __restrict__ Ohi, __half* __restrict__ Olo) {
    const uint32_t sb = smem_u32(dyn_smem);
    const int tid = threadIdx.x;
    const int wid = tid >> 5;
    const int lane = tid & 31;
    const int h = blockIdx.y & 15;
    const int b = blockIdx.y >> 4;
    const int q0 = blockIdx.x << 7;
    const int g = lane >> 2;
    const int c = lane & 3;

    // --- stage Q (fits in stage 0; recycled after frag load) ---
    {
        const size_t qg = ((size_t)(b * QLEN + q0)) * HIDDEN + h * HEAD_DIM;
#pragma unroll
        for (int i = 0; i < 8; i++) {
            int slot = tid + i * 256;
            int r = slot >> 4, c16 = slot & 15;
            uint32_t so = (uint32_t)r * ROWB + (uint32_t)c16 * 16u;
            cp16(sb + so, Qh + qg + (size_t)r * HIDDEN + c16 * 8);
        }
        CP_COMMIT();
    }

    const uint32_t a_off = (uint32_t)(lane & 15) * ROWB + (uint32_t)((lane >> 4) << 4);
    const uint32_t b_row = (uint32_t)((lane & 7) + ((lane >> 4) << 3));
    const uint32_t b_off = b_row * ROWB + (uint32_t)(((lane >> 3) & 1) << 4);
    const uint32_t v_row = (uint32_t)((lane & 7) + (((lane >> 3) & 1) << 3));
    const uint32_t v_off = v_row * ROWB + (uint32_t)(((lane >> 4) & 1) << 4);

    // --- load Q fragments into persistent registers ---
    uint32_t qh[8][4];
    {
        asm volatile("cp.async.wait_group 0;" ::: "memory");
        __syncthreads();
        const uint32_t aQ = sb + (uint32_t)(16 * wid) * ROWB + a_off;
#pragma unroll
        for (int ks = 0; ks < 8; ks++)
            ldsm4(qh[ks], aQ + (uint32_t)(ks * 32));
        __syncthreads();  // Q region recycled as KV stage 0
    }

    auto load_kv = [&](int cc) {
        const uint32_t stg = sb + (uint32_t)(cc % 3) * STG_B;
        const int kb = cc << 6;
#pragma unroll
        for (int i = 0; i < 4; i++) {
            int slot = tid + i * 256;
            int r = slot >> 4, c16 = slot & 15;
            uint32_t so = (uint32_t)r * ROWB + (uint32_t)c16 * 16u;
            size_t go = (size_t)(kb + r) * HIDDEN + h * HEAD_DIM + c16 * 8;
            cp16(stg + 0 * KT_B + so, Kh + go);
            cp16(stg + 1 * KT_B + so, Vh + go);
        }
        CP_COMMIT();
    };
    load_kv(0);
    load_kv(1);

    float m0 = -1e30f, m1 = -1e30f, l0 = 0.f, l1 = 0.f;
    float o[16][4];
#pragma unroll
    for (int ni = 0; ni < 16; ni++)
#pragma unroll
        for (int j = 0; j < 4; j++) o[ni][j] = 0.f;

    for (int ch = 0; ch < 64; ch++) {
        if (ch == 63)
            asm volatile("cp.async.wait_group 0;" ::: "memory");
        else
            asm volatile("cp.async.wait_group 1;" ::: "memory");
        __syncthreads();
        if (ch + 2 < 64) load_kv(ch + 2);

        const uint32_t stg = sb + (uint32_t)(ch % 3) * STG_B;
        const uint32_t sK = stg + 0 * KT_B + b_off;
        const uint32_t sV = stg + 1 * KT_B + v_off;

        // --- S = Q K^T (single pass, fp16 operands) ---
        float s[8][4];
#pragma unroll
        for (int ni = 0; ni < 8; ni++)
#pragma unroll
            for (int j = 0; j < 4; j++) s[ni][j] = 0.f;

#pragma unroll
        for (int ks = 0; ks < 8; ks++) {
            const uint32_t ko = (uint32_t)(ks * 32);
#pragma unroll
            for (int j = 0; j < 4; j++) {
                uint32_t bh[4];
                ldsm4(bh, sK + (uint32_t)(16 * j) * ROWB + ko);
                mma16816(s[2 * j],     qh[ks], bh + 0);
                mma16816(s[2 * j + 1], qh[ks], bh + 2);
            }
        }

        // --- online softmax (warp-local) ---
        float mx0 = -1e30f, mx1 = -1e30f;
#pragma unroll
        for (int ni = 0; ni < 8; ni++) {
#pragma unroll
            for (int j = 0; j < 4; j++) s[ni][j] *= SCALE_F;
            mx0 = fmaxf(mx0, fmaxf(s[ni][0], s[ni][1]));
            mx1 = fmaxf(mx1, fmaxf(s[ni][2], s[ni][3]));
        }
        mx0 = fmaxf(mx0, __shfl_xor_sync(0xffffffffu, mx0, 1));
        mx0 = fmaxf(mx0, __shfl_xor_sync(0xffffffffu, mx0, 2));
        mx1 = fmaxf(mx1, __shfl_xor_sync(0xffffffffu, mx1, 1));
        mx1 = fmaxf(mx1, __shfl_xor_sync(0xffffffffu, mx1, 2));
        const float nm0 = fmaxf(m0, mx0);
        const float nm1 = fmaxf(m1, mx1);
        const float al0 = __expf(m0 - nm0);
        const float al1 = __expf(m1 - nm1);
        float sum0 = 0.f, sum1 = 0.f;
#pragma unroll
        for (int ni = 0; ni < 8; ni++) {
            s[ni][0] = __expf(s[ni][0] - nm0);
            s[ni][1] = __expf(s[ni][1] - nm0);
            s[ni][2] = __expf(s[ni][2] - nm1);
            s[ni][3] = __expf(s[ni][3] - nm1);
            sum0 += s[ni][0] + s[ni][1];
            sum1 += s[ni][2] + s[ni][3];
        }
        sum0 += __shfl_xor_sync(0xffffffffu, sum0, 1);
        sum0 += __shfl_xor_sync(0xffffffffu, sum0, 2);
        sum1 += __shfl_xor_sync(0xffffffffu, sum1, 1);
        sum1 += __shfl_xor_sync(0xffffffffu, sum1, 2);
        l0 = l0 * al0 + sum0;
        l1 = l1 * al1 + sum1;
        m0 = nm0;
        m1 = nm1;
#pragma unroll
        for (int ni = 0; ni < 16; ni++) {
            o[ni][0] *= al0; o[ni][1] *= al0;
            o[ni][2] *= al1; o[ni][3] *= al1;
        }

        // --- O += P V (single pass, P rounded to fp16) ---
#pragma unroll
        for (int ks = 0; ks < 4; ks++) {
            uint32_t ph[4];
            ph[0] = packh(s[2 * ks][0],     s[2 * ks][1]);
            ph[1] = packh(s[2 * ks][2],     s[2 * ks][3]);
            ph[2] = packh(s[2 * ks + 1][0], s[2 * ks + 1][1]);
            ph[3] = packh(s[2 * ks + 1][2], s[2 * ks + 1][3]);
            const uint32_t vro = (uint32_t)(16 * ks) * ROWB;
#pragma unroll
            for (int j = 0; j < 8; j++) {
                uint32_t vh[4];
                ldsm4t(vh, sV + vro + (uint32_t)(32 * j));
                mma16816(o[2 * j],     ph, vh + 0);
                mma16816(o[2 * j + 1], ph, vh + 2);
            }
        }
    }

    // epilogue: normalized O -> fused fp16 hi/lo (A-side of O-projection)
    const float inv0 = 1.0f / l0;
    const float inv1 = 1.0f / l1;
    const int row0 = q0 + 16 * wid + g;
    const size_t base0 = ((size_t)(b * QLEN + row0)) * HIDDEN + h * HEAD_DIM;
    const size_t base1 = base0 + (size_t)8 * HIDDEN;
#pragma unroll
    for (int ni = 0; ni < 16; ni++) {
        const int col = 8 * ni + 2 * c;
        uint32_t h0, l0b, h1, l1b;
        buildp(h0, l0b, o[ni][0] * inv0, o[ni][1] * inv0);
        buildp(h1, l1b, o[ni][2] * inv1, o[ni][3] * inv1);
        *(uint32_t*)(Ohi + base0 + col) = h0;
        *(uint32_t*)(Olo + base0 + col) = l0b;
        *(uint32_t*)(Ohi + base1 + col) = h1;
        *(uint32_t*)(Olo + base1 + col) = l1b;
    }
}

// ---------------------------------------------------------------------------
// kernel_launch
// ---------------------------------------------------------------------------
extern "C" void kernel_launch(void* const* d_in, const int* in_sizes, int n_in,
                              void* d_out, int out_size) {
    const float* query = (const float*)d_in[0];
    const float* kv_k  = (const float*)d_in[1];
    const float* kv_v  = (const float*)d_in[2];
    const float* Wq    = (const float*)d_in[3];
    const float* Wo    = (const float*)d_in[4];
    float* out = (float*)d_out;

    __half *ahi, *alo, *bh, *qh, *kh, *vh;
    cudaGetSymbolAddress((void**)&ahi, g_Ahi);
    cudaGetSymbolAddress((void**)&alo, g_Alo);
    cudaGetSymbolAddress((void**)&bh, g_Bh);
    cudaGetSymbolAddress((void**)&qh, g_Qh);
    cudaGetSymbolAddress((void**)&kh, g_Kh);
    cudaGetSymbolAddress((void**)&vh, g_Vh);

    cudaFuncSetAttribute(gemm_f16x2, cudaFuncAttributeMaxDynamicSharedMemorySize,
                         GEMM_SMEM);
    cudaFuncSetAttribute(attn_mma, cudaFuncAttributeMaxDynamicSharedMemorySize,
                         ATTN_SMEM);

    const int NA4 = MROWS * HIDDEN / 4;
    const int NW4 = HIDDEN * HIDDEN / 4;
    const int NKV4 = KVLEN * HIDDEN / 4;
    dim3 gemm_grid(HIDDEN / 128, MROWS / 128);  // (16, 64)

    // Q projection: query split (A-side 2-pass), Wq rounded; output Q fp16 only
    split_fp16<<<2048, 256>>>((const float4*)query, (uint2*)ahi, (uint2*)alo, NA4);
    conv_fp16<<<1024, 256>>>((const float4*)Wq, (uint2*)bh, NW4);
    gemm_f16x2<<<gemm_grid, 256, GEMM_SMEM>>>(ahi, alo, bh, qh, nullptr, nullptr);

    // KV converts
    conv_fp16<<<1024, 256>>>((const float4*)kv_k, (uint2*)kh, NKV4);
    conv_fp16<<<1024, 256>>>((const float4*)kv_v, (uint2*)vh, NKV4);

    // Attention (pure fp16 operands; epilogue writes O hi/lo into A buffers)
    dim3 attn_grid(QLEN / 128, BATCH * HEADS);  // (8, 128)
    attn_mma<<<attn_grid, 256, ATTN_SMEM>>>(qh, kh, vh, ahi, alo);

    // Output projection (A-side 2-pass on O hi/lo; fp32 out)
    conv_fp16<<<1024, 256>>>((const float4*)Wo, (uint2*)bh, NW4);
    gemm_f16x2<<<gemm_grid, 256, GEMM_SMEM>>>(ahi, alo, bh,
                                              nullptr, nullptr, out);
}